// round 1
// baseline (speedup 1.0000x reference)
#include <cuda_runtime.h>
#include <math.h>

#define CB 16
#define CS 512
#define CN 321
#define CD 512
#define CDF 2048
#define CP 96
#define CBN (CB*CN)            /* 5136  */
#define BND ((size_t)CBN*CD)   /* 2629632 */
#define BNMD ((size_t)CBN*4*CD)/* 10518528 */
#define ATT ((size_t)CB*4*CD*CD) /* 16777216 */
#define ALPHA_ 0.3f

// ---------------- workspace ----------------
// offsets (floats)
#define O_XT   ((size_t)0)
#define O_H    (O_XT + BND)
#define O_MEAN (O_H + BND)
#define O_STD  (O_MEAN + CBN)
#define O_COEF (O_STD + CBN)
#define O_Q    (O_COEF + BNMD)
#define O_K    (O_Q + BNMD)
#define O_V    (O_K + BNMD)
#define O_QA   (O_V + BNMD)
#define O_KA   (O_QA + BNMD)
#define O_DOT  (O_KA + BNMD)
#define O_QN2  (O_DOT + ATT)
#define O_KN2  (O_QN2 + (size_t)CB*4*CD)
#define O_AO   (O_KN2 + (size_t)CB*4*CD)
#define O_REC  (O_AO + BNMD)
#define O_ATT  (O_REC + BND)
#define O_X1   (O_ATT + BND)
#define O_FF   (O_X1 + BND)
#define O_Y2   (O_FF + (size_t)CBN*CDF)
#define O_DEC  (O_Y2 + BND)
#define WS_TOTAL (O_DEC + (size_t)CBN*CP)

__device__ float g_ws[WS_TOTAL];

// ---------------- generic batched NT GEMM ----------------
// C[row,col] = sum_k A[row*lda+k] * B[col*ldb+k]  (+bias[col], optional gelu)
// batch z: zh=z/bdiv, zl=z%bdiv; per-operand offsets zh*sXh + zl*sXl
// C stored at row*ldcr + col*ldcc (allows transposed scatter stores)
__global__ void gemm_nt(
    const float* __restrict__ A, const float* __restrict__ Bm,
    float* __restrict__ C, const float* __restrict__ bias,
    int M, int Nn, int Kd,
    int lda, int ldb,
    long long ldcr, long long ldcc,
    int bdiv,
    long long sAh, long long sAl,
    long long sBh, long long sBl,
    long long sCh, long long sCl,
    int act)
{
    int z = blockIdx.z;
    int zh = z / bdiv, zl = z % bdiv;
    A  += zh * sAh + zl * sAl;
    Bm += zh * sBh + zl * sBl;
    C  += zh * sCh + zl * sCl;

    __shared__ float As[16][64];
    __shared__ float Bs[16][64];

    int tx = threadIdx.x, ty = threadIdx.y;
    int tid = ty * 16 + tx;
    int m0 = blockIdx.x * 64, n0 = blockIdx.y * 64;

    float acc[4][4] = {};

    for (int k0 = 0; k0 < Kd; k0 += 16) {
        #pragma unroll
        for (int i = 0; i < 4; i++) {
            int idx = tid + i * 256;
            int m = idx >> 4, k = idx & 15;
            int gm = m0 + m, gk = k0 + k;
            As[k][m] = (gm < M  && gk < Kd) ? A[(long long)gm * lda + gk] : 0.f;
            int gn = n0 + m;
            Bs[k][m] = (gn < Nn && gk < Kd) ? Bm[(long long)gn * ldb + gk] : 0.f;
        }
        __syncthreads();
        #pragma unroll
        for (int kk = 0; kk < 16; kk++) {
            float4 a4 = *(const float4*)&As[kk][ty * 4];
            float4 b4 = *(const float4*)&Bs[kk][tx * 4];
            float av[4] = {a4.x, a4.y, a4.z, a4.w};
            float bv[4] = {b4.x, b4.y, b4.z, b4.w};
            #pragma unroll
            for (int i = 0; i < 4; i++)
                #pragma unroll
                for (int j = 0; j < 4; j++)
                    acc[i][j] += av[i] * bv[j];
        }
        __syncthreads();
    }
    #pragma unroll
    for (int i = 0; i < 4; i++) {
        int row = m0 + ty * 4 + i;
        if (row >= M) continue;
        #pragma unroll
        for (int j = 0; j < 4; j++) {
            int col = n0 + tx * 4 + j;
            if (col >= Nn) continue;
            float v = acc[i][j];
            if (bias) v += bias[col];
            if (act == 1) v = 0.5f * v * (1.f + erff(v * 0.70710678118654752f));
            C[(long long)row * ldcr + (long long)col * ldcc] = v;
        }
    }
}

// ---------------- per-(b,n) stats over S ----------------
__global__ void stats_kernel(const float* __restrict__ x, float* __restrict__ mean,
                             float* __restrict__ stdv)
{
    int bn = blockIdx.x;
    int b = bn / CN, n = bn % CN;
    const float* p = x + (long long)b * CS * CN + n;
    float s = 0.f, s2 = 0.f;
    for (int i = threadIdx.x; i < CS; i += blockDim.x) {
        float v = p[(long long)i * CN];
        s += v; s2 += v * v;
    }
    __shared__ float rs[128], rq[128];
    rs[threadIdx.x] = s; rq[threadIdx.x] = s2; __syncthreads();
    for (int o = 64; o > 0; o >>= 1) {
        if (threadIdx.x < o) { rs[threadIdx.x] += rs[threadIdx.x + o]; rq[threadIdx.x] += rq[threadIdx.x + o]; }
        __syncthreads();
    }
    if (threadIdx.x == 0) {
        float mu = rs[0] / CS;
        float var = rq[0] / CS - mu * mu;
        mean[bn] = mu;
        stdv[bn] = sqrtf(var + 1e-5f);
    }
}

// xt[(b,n),s] = (x_enc[b,s,n]-mean)/std
__global__ void norm_t_kernel(const float* __restrict__ x, const float* __restrict__ mean,
                              const float* __restrict__ stdv, float* __restrict__ xt)
{
    long long idx = (long long)blockIdx.x * blockDim.x + threadIdx.x;
    if (idx >= (long long)BND) return;
    int s = (int)(idx & (CS - 1));
    long long bn = idx >> 9;
    int b = (int)(bn / CN), n = (int)(bn % CN);
    xt[idx] = (x[((long long)b * CS + s) * CN + n] - mean[bn]) / stdv[bn];
}

// ---------------- SWT decomposition ----------------
// coeffs m: 0=approx(final), 1=det dil4, 2=det dil2, 3=det dil1
__global__ void swt_dec_kernel(const float* __restrict__ h,
                               const float* __restrict__ f0g, const float* __restrict__ f1g,
                               float* __restrict__ coef)
{
    int bn = blockIdx.x; int n = bn % CN;
    __shared__ float a[CD], b[CD];
    const float* hp = h + (long long)bn * CD;
    for (int d = threadIdx.x; d < CD; d += blockDim.x) a[d] = hp[d];
    float l0[3], l1[3];
    #pragma unroll
    for (int t = 0; t < 3; t++) { l0[t] = f0g[n * 3 + t]; l1[t] = f1g[n * 3 + t]; }
    __syncthreads();
    float* cf = coef + (long long)bn * 4 * CD;
    // dil=1, taps d-1,d,d+1
    for (int d = threadIdx.x; d < CD; d += blockDim.x) {
        int im = (d - 1) & 511, ip = (d + 1) & 511;
        cf[3 * CD + d] = l1[0] * a[im] + l1[1] * a[d] + l1[2] * a[ip];
        b[d]           = l0[0] * a[im] + l0[1] * a[d] + l0[2] * a[ip];
    }
    __syncthreads();
    // dil=2, taps d-1,d+1,d+3
    for (int d = threadIdx.x; d < CD; d += blockDim.x) {
        int i0 = (d - 1) & 511, i1 = (d + 1) & 511, i2 = (d + 3) & 511;
        cf[2 * CD + d] = l1[0] * b[i0] + l1[1] * b[i1] + l1[2] * b[i2];
        a[d]           = l0[0] * b[i0] + l0[1] * b[i1] + l0[2] * b[i2];
    }
    __syncthreads();
    // dil=4, taps d-2,d+2,d+6
    for (int d = threadIdx.x; d < CD; d += blockDim.x) {
        int i0 = (d - 2) & 511, i1 = (d + 2) & 511, i2 = (d + 6) & 511;
        cf[1 * CD + d] = l1[0] * a[i0] + l1[1] * a[i1] + l1[2] * a[i2];
        cf[0 * CD + d] = l0[0] * a[i0] + l0[1] * a[i1] + l0[2] * a[i2];
    }
}

// ---------------- SWT reconstruction ----------------
__global__ void swt_rec_kernel(const float* __restrict__ c,
                               const float* __restrict__ g0g, const float* __restrict__ g1g,
                               float* __restrict__ out)
{
    int bn = blockIdx.x; int n = bn % CN;
    const float* cp = c + (long long)bn * 4 * CD;
    __shared__ float a[CD], b[CD], det[CD];
    float f0[3], f1[3];
    #pragma unroll
    for (int t = 0; t < 3; t++) { f0[t] = g0g[n * 3 + t]; f1[t] = g1g[n * 3 + t]; }
    for (int d = threadIdx.x; d < CD; d += blockDim.x) { a[d] = cp[d]; det[d] = cp[CD + d]; }
    __syncthreads();
    // dil=4, taps d-6,d-2,d+2
    for (int d = threadIdx.x; d < CD; d += blockDim.x) {
        int i0 = (d - 6) & 511, i1 = (d - 2) & 511, i2 = (d + 2) & 511;
        b[d] = 0.5f * (f0[0] * a[i0] + f0[1] * a[i1] + f0[2] * a[i2]
                     + f1[0] * det[i0] + f1[1] * det[i1] + f1[2] * det[i2]);
    }
    __syncthreads();
    for (int d = threadIdx.x; d < CD; d += blockDim.x) det[d] = cp[2 * CD + d];
    __syncthreads();
    // dil=2, taps d-3,d-1,d+1
    for (int d = threadIdx.x; d < CD; d += blockDim.x) {
        int i0 = (d - 3) & 511, i1 = (d - 1) & 511, i2 = (d + 1) & 511;
        a[d] = 0.5f * (f0[0] * b[i0] + f0[1] * b[i1] + f0[2] * b[i2]
                     + f1[0] * det[i0] + f1[1] * det[i1] + f1[2] * det[i2]);
    }
    __syncthreads();
    for (int d = threadIdx.x; d < CD; d += blockDim.x) det[d] = cp[3 * CD + d];
    __syncthreads();
    // dil=1, taps d-1,d,d+1
    float* op = out + (long long)bn * CD;
    for (int d = threadIdx.x; d < CD; d += blockDim.x) {
        int i0 = (d - 1) & 511, i2 = (d + 1) & 511;
        op[d] = 0.5f * (f0[0] * a[i0] + f0[1] * a[d] + f0[2] * a[i2]
                      + f1[0] * det[i0] + f1[1] * det[d] + f1[2] * det[i2]);
    }
}

// ---------------- transpose [b][n][m][e] -> [b][m][e][n] ----------------
__global__ void trans_kernel(const float* __restrict__ in, float* __restrict__ out)
{
    int z = blockIdx.z; int b = z >> 2, m = z & 3;
    __shared__ float t[32][33];
    int e0 = blockIdx.x * 32, n0 = blockIdx.y * 32;
    int tx = threadIdx.x, ty = threadIdx.y;
    #pragma unroll
    for (int j = 0; j < 4; j++) {
        int e = e0 + tx, n = n0 + ty + j * 8;
        if (e < CD && n < CN)
            t[ty + j * 8][tx] = in[(((long long)b * CN + n) * 4 + m) * CD + e];
    }
    __syncthreads();
    #pragma unroll
    for (int j = 0; j < 4; j++) {
        int n = n0 + tx, e = e0 + ty + j * 8;
        if (n < CN && e < CD)
            out[(((long long)b * 4 + m) * CD + e) * CN + n] = t[tx][ty + j * 8];
    }
}

// ---------------- row squared-norm (rows of length CN) ----------------
__global__ void rowsq_kernel(const float* __restrict__ in, float* __restrict__ out)
{
    int r = blockIdx.x;
    const float* p = in + (long long)r * CN;
    float s = 0.f;
    for (int i = threadIdx.x; i < CN; i += blockDim.x) { float v = p[i]; s += v * v; }
    __shared__ float rs[128];
    rs[threadIdx.x] = s; __syncthreads();
    for (int o = 64; o > 0; o >>= 1) {
        if (threadIdx.x < o) rs[threadIdx.x] += rs[threadIdx.x + o];
        __syncthreads();
    }
    if (threadIdx.x == 0) out[r] = rs[0];
}

// ---------------- wedge score + softmax (in place on dot) ----------------
__global__ void score_softmax_kernel(float* __restrict__ dot,
                                     const float* __restrict__ qn2,
                                     const float* __restrict__ kn2)
{
    int row = blockIdx.x;          // z*512 + l
    int z = row >> 9;
    float q2 = qn2[row];
    float* p = dot + (long long)row * CD;
    const float* k2 = kn2 + (long long)z * CD;
    const float scale = 1.f / sqrtf((float)CN);
    int t = threadIdx.x;           // 256 threads, 2 elems each
    float sc[2];
    float mx = -1e30f;
    #pragma unroll
    for (int j = 0; j < 2; j++) {
        int s = t + j * 256;
        float d = p[s];
        float w = sqrtf(fmaxf(q2 * k2[s] - d * d, 0.f) + 1e-8f);
        float v = ((1.f - ALPHA_) * d + ALPHA_ * w) * scale;
        sc[j] = v;
        mx = fmaxf(mx, v);
    }
    __shared__ float red[256];
    red[t] = mx; __syncthreads();
    for (int o = 128; o > 0; o >>= 1) {
        if (t < o) red[t] = fmaxf(red[t], red[t + o]);
        __syncthreads();
    }
    mx = red[0]; __syncthreads();
    float sum = 0.f;
    #pragma unroll
    for (int j = 0; j < 2; j++) { sc[j] = expf(sc[j] - mx); sum += sc[j]; }
    red[t] = sum; __syncthreads();
    for (int o = 128; o > 0; o >>= 1) {
        if (t < o) red[t] += red[t + o];
        __syncthreads();
    }
    float inv = 1.f / red[0];
    #pragma unroll
    for (int j = 0; j < 2; j++) p[t + j * 256] = sc[j] * inv;
}

// ---------------- add + layernorm ----------------
__global__ void add_ln_kernel(const float* __restrict__ x, const float* __restrict__ y,
                              const float* __restrict__ g, const float* __restrict__ bb,
                              float* __restrict__ out)
{
    int bn = blockIdx.x;
    const float* xp = x + (long long)bn * CD;
    const float* yp = y ? y + (long long)bn * CD : nullptr;
    int t = threadIdx.x;   // 256 threads, 2 per thread
    float v[2];
    float s = 0.f;
    #pragma unroll
    for (int j = 0; j < 2; j++) {
        int d = t + j * 256;
        v[j] = xp[d] + (yp ? yp[d] : 0.f);
        s += v[j];
    }
    __shared__ float red[256];
    red[t] = s; __syncthreads();
    for (int o = 128; o > 0; o >>= 1) { if (t < o) red[t] += red[t + o]; __syncthreads(); }
    float mu = red[0] / CD; __syncthreads();
    float s2 = 0.f;
    #pragma unroll
    for (int j = 0; j < 2; j++) { float dv = v[j] - mu; s2 += dv * dv; }
    red[t] = s2; __syncthreads();
    for (int o = 128; o > 0; o >>= 1) { if (t < o) red[t] += red[t + o]; __syncthreads(); }
    float inv = 1.f / sqrtf(red[0] / CD + 1e-5f);
    #pragma unroll
    for (int j = 0; j < 2; j++) {
        int d = t + j * 256;
        out[(long long)bn * CD + d] = (v[j] - mu) * inv * g[d] + bb[d];
    }
}

// ---------------- final output de-normalization ----------------
__global__ void out_kernel(const float* __restrict__ dec, const float* __restrict__ mean,
                           const float* __restrict__ stdv, float* __restrict__ out)
{
    int idx = blockIdx.x * blockDim.x + threadIdx.x;
    if (idx >= CB * CP * CN) return;
    int n = idx % CN;
    int p = (idx / CN) % CP;
    int b = idx / (CN * CP);
    int bn = b * CN + n;
    out[idx] = dec[(long long)bn * CP + p] * stdv[bn] + mean[bn];
}

__global__ void aux_out_kernel(const float* __restrict__ mean, const float* __restrict__ stdv,
                               float* __restrict__ out)
{
    int i = blockIdx.x * blockDim.x + threadIdx.x;
    if (i >= CBN) return;
    out[CB * CP * CN + i] = mean[i];
    out[CB * CP * CN + CBN + i] = stdv[i];
}

// ---------------- host orchestration ----------------
static void launch_gemm(const float* A, const float* B, float* C, const float* bias,
                        int M, int Nn, int Kd, int lda, int ldb,
                        long long ldcr, long long ldcc,
                        int batches, int bdiv,
                        long long sAh, long long sAl,
                        long long sBh, long long sBl,
                        long long sCh, long long sCl, int act)
{
    dim3 grid((M + 63) / 64, (Nn + 63) / 64, batches);
    dim3 blk(16, 16);
    gemm_nt<<<grid, blk>>>(A, B, C, bias, M, Nn, Kd, lda, ldb, ldcr, ldcc,
                           bdiv, sAh, sAl, sBh, sBl, sCh, sCl, act);
}

extern "C" void kernel_launch(void* const* d_in, const int* in_sizes, int n_in,
                              void* d_out, int out_size)
{
    (void)in_sizes; (void)n_in;
    const float* x_enc  = (const float*)d_in[0];
    const float* emb_W  = (const float*)d_in[1];
    const float* emb_b  = (const float*)d_in[2];
    const float* h0     = (const float*)d_in[3];
    const float* h1     = (const float*)d_in[4];
    const float* g0     = (const float*)d_in[5];
    const float* g1     = (const float*)d_in[6];
    const float* Wq     = (const float*)d_in[7];
    const float* bq     = (const float*)d_in[8];
    const float* Wk     = (const float*)d_in[9];
    const float* bk     = (const float*)d_in[10];
    const float* Wv     = (const float*)d_in[11];
    const float* bv     = (const float*)d_in[12];
    const float* Wo     = (const float*)d_in[13];
    const float* bo     = (const float*)d_in[14];
    const float* W1     = (const float*)d_in[15];
    const float* b1     = (const float*)d_in[16];
    const float* W2     = (const float*)d_in[17];
    const float* b2     = (const float*)d_in[18];
    const float* ln1_g  = (const float*)d_in[19];
    const float* ln1_b  = (const float*)d_in[20];
    const float* ln2_g  = (const float*)d_in[21];
    const float* ln2_b  = (const float*)d_in[22];
    const float* lnf_g  = (const float*)d_in[23];
    const float* lnf_b  = (const float*)d_in[24];
    const float* proj_W = (const float*)d_in[25];
    const float* proj_b = (const float*)d_in[26];

    float* ws = nullptr;
    cudaGetSymbolAddress((void**)&ws, g_ws);

    float* xt   = ws + O_XT;
    float* h    = ws + O_H;
    float* mean = ws + O_MEAN;
    float* stdv = ws + O_STD;
    float* coef = ws + O_COEF;
    float* q    = ws + O_Q;
    float* k    = ws + O_K;
    float* v    = ws + O_V;
    float* qa   = ws + O_QA;
    float* ka   = ws + O_KA;
    float* dot  = ws + O_DOT;
    float* qn2  = ws + O_QN2;
    float* kn2  = ws + O_KN2;
    float* ao   = ws + O_AO;
    float* rec  = ws + O_REC;
    float* att  = ws + O_ATT;
    float* x1   = ws + O_X1;
    float* ff   = ws + O_FF;
    float* y2   = ws + O_Y2;
    float* dec  = ws + O_DEC;

    // 1) stats + normalize-transpose
    stats_kernel<<<CBN, 128>>>(x_enc, mean, stdv);
    norm_t_kernel<<<(int)((BND + 255) / 256), 256>>>(x_enc, mean, stdv, xt);

    // 2) embedding: h[(b,n),d] = sum_s xt*emb_W[d,s] + emb_b[d]
    launch_gemm(xt, emb_W, h, emb_b, CBN, CD, CS, CS, CS, CD, 1,
                1, 1, 0, 0, 0, 0, 0, 0, 0);

    const long long ZA = (long long)CD * CN;       // 164352
    const long long ZD = (long long)CD * CD;       // 262144
    const long long BSTR = (long long)CN * 4 * CD; // 657408

    for (int l = 0; l < 2; l++) {
        swt_dec_kernel<<<CBN, 256>>>(h, h0 + (long long)l * CN * 3, h1 + (long long)l * CN * 3, coef);

        // QKV projections: (CBN*4) x CD x CD
        launch_gemm(coef, Wq + (long long)l * CD * CD, q, bq + (long long)l * CD,
                    CBN * 4, CD, CD, CD, CD, CD, 1, 1, 1, 0, 0, 0, 0, 0, 0, 0);
        launch_gemm(coef, Wk + (long long)l * CD * CD, k, bk + (long long)l * CD,
                    CBN * 4, CD, CD, CD, CD, CD, 1, 1, 1, 0, 0, 0, 0, 0, 0, 0);
        launch_gemm(coef, Wv + (long long)l * CD * CD, v, bv + (long long)l * CD,
                    CBN * 4, CD, CD, CD, CD, CD, 1, 1, 1, 0, 0, 0, 0, 0, 0, 0);

        // transpose q,k to [b][m][e][n]
        {
            dim3 g2(16, 11, CB * 4), b2d(32, 8);
            trans_kernel<<<g2, b2d>>>(q, qa);
            trans_kernel<<<g2, b2d>>>(k, ka);
        }
        rowsq_kernel<<<CB * 4 * CD, 128>>>(qa, qn2);
        rowsq_kernel<<<CB * 4 * CD, 128>>>(ka, kn2);

        // dot[l,s] = sum_n qa[l,n]*ka[s,n], batched over z=b*4+m
        launch_gemm(qa, ka, dot, nullptr, CD, CD, CN, CN, CN, CD, 1,
                    CB * 4, 1, ZA, 0, ZA, 0, ZD, 0, 0);

        score_softmax_kernel<<<CB * 4 * CD, 256>>>(dot, qn2, kn2);

        // AV: O[l,n] = sum_s A[l,s] * v[b,n,m,s]; scatter into coeffs layout [b][n][m][l]
        launch_gemm(dot, v, ao, nullptr, CD, CN, CD, CD, 4 * CD, 1, 4 * CD,
                    CB * 4, 4,
                    4 * ZD, ZD,        // A: z*ZD
                    BSTR, CD,          // B: b*BSTR + m*CD
                    BSTR, CD,          // C: b*BSTR + m*CD
                    0);

        swt_rec_kernel<<<CBN, 256>>>(ao, g0 + (long long)l * CN * 3, g1 + (long long)l * CN * 3, rec);

        // Wo projection
        launch_gemm(rec, Wo + (long long)l * CD * CD, att, bo + (long long)l * CD,
                    CBN, CD, CD, CD, CD, CD, 1, 1, 1, 0, 0, 0, 0, 0, 0, 0);

        add_ln_kernel<<<CBN, 256>>>(h, att, ln1_g + (long long)l * CD, ln1_b + (long long)l * CD, x1);

        // FFN
        launch_gemm(x1, W1 + (long long)l * CDF * CD, ff, b1 + (long long)l * CDF,
                    CBN, CDF, CD, CD, CD, CDF, 1, 1, 1, 0, 0, 0, 0, 0, 0, 1);
        launch_gemm(ff, W2 + (long long)l * CD * CDF, y2, b2 + (long long)l * CD,
                    CBN, CD, CDF, CDF, CDF, CD, 1, 1, 1, 0, 0, 0, 0, 0, 0, 0);

        add_ln_kernel<<<CBN, 256>>>(x1, y2, ln2_g + (long long)l * CD, ln2_b + (long long)l * CD, h);
    }

    // final LN + projection + de-normalize
    add_ln_kernel<<<CBN, 256>>>(h, nullptr, lnf_g, lnf_b, x1);
    launch_gemm(x1, proj_W, dec, proj_b, CBN, CP, CD, CD, CD, CP, 1,
                1, 1, 0, 0, 0, 0, 0, 0, 0);

    out_kernel<<<(CB * CP * CN + 255) / 256, 256>>>(dec, mean, stdv, (float*)d_out);
    if (out_size >= CB * CP * CN + 2 * CBN) {
        aux_out_kernel<<<(CBN + 255) / 256, 256>>>(mean, stdv, (float*)d_out);
    }
}

// round 4
// speedup vs baseline: 4.4914x; 4.4914x over previous
#include <cuda_runtime.h>
#include <math.h>
#include <stdint.h>

#define CB 16
#define CS 512
#define CN 321
#define CD 512
#define CDF 2048
#define CP 96
#define KPAD 352                 /* CN padded to mult of 32 */
#define CBN (CB*CN)              /* 5136  */
#define BND ((size_t)CBN*CD)
#define BNMD ((size_t)CBN*4*CD)
#define QAPAD ((size_t)CB*4*CD*KPAD)
#define ATT ((size_t)CB*4*CD*CD)
#define ALPHA_ 0.3f

// ---------------- workspace (floats) ----------------
#define O_XT   ((size_t)0)
#define O_H    (O_XT + BND)
#define O_MEAN (O_H + BND)
#define O_STD  (O_MEAN + CBN)
#define O_COEF (O_STD + CBN)
#define O_Q    (O_COEF + BNMD)
#define O_K    (O_Q + BNMD)
#define O_V    (O_K + BNMD)
#define O_QA   (O_V + BNMD)
#define O_KA   (O_QA + QAPAD)
#define O_DOT  (O_KA + QAPAD)
#define O_QN2  (O_DOT + ATT)
#define O_KN2  (O_QN2 + (size_t)CB*4*CD)
#define O_AO   (O_KN2 + (size_t)CB*4*CD)
#define O_REC  (O_AO + BNMD)
#define O_ATT  (O_REC + BND)
#define O_X1   (O_ATT + BND)
#define O_FF   (O_X1 + BND)
#define O_Y2   (O_FF + (size_t)CBN*CDF)
#define O_DEC  (O_Y2 + BND)
#define WS_TOTAL (O_DEC + (size_t)CBN*CP)

__device__ float g_ws[WS_TOTAL];

// ---------------- smem helpers ----------------
__device__ __forceinline__ uint32_t smem_u32(const void* p) {
    uint32_t a;
    asm("{ .reg .u64 t; cvta.to.shared.u64 t, %1; cvt.u32.u64 %0, t; }" : "=r"(a) : "l"(p));
    return a;
}
__device__ __forceinline__ void cp16(uint32_t dst, const void* src, int sz) {
    asm volatile("cp.async.cg.shared.global [%0], [%1], 16, %2;"
                 :: "r"(dst), "l"(src), "r"(sz));
}
__device__ __forceinline__ void cp_commit() {
    asm volatile("cp.async.commit_group;" ::: "memory");
}
__device__ __forceinline__ void cp_wait1() {
    asm volatile("cp.async.wait_group 1;" ::: "memory");
}
__device__ __forceinline__ void cp_wait0() {
    asm volatile("cp.async.wait_group 0;" ::: "memory");
}

#define ASTRIDE 36
#define ABUF (128*ASTRIDE)             /* floats per buffer */
#define SMEM_DYN (4*ABUF*4)            /* 73728 bytes */

// async load 128 rows x 32 floats of a K-chunk into smem (stride 36), zero-pad OOB rows
__device__ __forceinline__ void load_chunk(const float* __restrict__ g, int rows, int ld,
                                           int k0, uint32_t smbase, int tid) {
    #pragma unroll
    for (int i = 0; i < 4; i++) {
        int idx = tid + (i << 8);
        int r = idx >> 3, c4 = (idx & 7) << 2;
        int ok = r < rows;
        const float* src = g + (long long)(ok ? r : 0) * ld + k0 + c4;
        cp16(smbase + (uint32_t)(r * ASTRIDE + c4) * 4u, src, ok ? 16 : 0);
    }
}

// ============ generic batched NT GEMM via mma.sync tf32 ============
// C[row,col] = sum_k A[row,k]*B[col,k] (+bias[col], optional gelu)
// batch z: zh=z/bdiv, zl=z%bdiv; offsets zh*sXh+zl*sXl. C at row*ldcr+col*ldcc.
__global__ __launch_bounds__(256, 2) void gemm_tc(
    const float* __restrict__ A, const float* __restrict__ Bm,
    float* __restrict__ C, const float* __restrict__ bias,
    int M, int Nn, int Kd, int lda, int ldb,
    long long ldcr, long long ldcc, int bdiv,
    long long sAh, long long sAl, long long sBh, long long sBl,
    long long sCh, long long sCl, int act)
{
    extern __shared__ float sm[];
    const int tid = threadIdx.x;
    const int wid = tid >> 5, lane = tid & 31;
    const int gid = lane >> 2, tig = lane & 3;
    const int wr = wid & 3, wc = wid >> 2;   // warp 32-row block, 64-col block

    int z = blockIdx.z;
    int zh = z / bdiv, zl = z % bdiv;
    A  += zh * sAh + zl * sAl;
    Bm += zh * sBh + zl * sBl;
    C  += zh * sCh + zl * sCl;

    int m0 = blockIdx.x * 128, n0 = blockIdx.y * 128;
    int mrem = M - m0, nrem = Nn - n0;
    const float* Ag = A + (long long)m0 * lda;
    const float* Bg = Bm + (long long)n0 * ldb;

    uint32_t smb = smem_u32(sm);
    const uint32_t aoff[2] = { smb, smb + ABUF * 4 };
    const uint32_t boff[2] = { smb + 2 * ABUF * 4, smb + 3 * ABUF * 4 };

    float c[2][8][4];
    #pragma unroll
    for (int i = 0; i < 2; i++)
        #pragma unroll
        for (int j = 0; j < 8; j++)
            #pragma unroll
            for (int r = 0; r < 4; r++) c[i][j][r] = 0.f;

    const int NC = Kd >> 5;
    // prologue: chunk 0
    load_chunk(Ag, mrem, lda, 0, aoff[0], tid);
    load_chunk(Bg, nrem, ldb, 0, boff[0], tid);
    cp_commit();

    for (int ch = 0; ch < NC; ch++) {
        int cur = ch & 1;
        if (ch + 1 < NC) {
            int nxt = cur ^ 1;
            load_chunk(Ag, mrem, lda, (ch + 1) << 5, aoff[nxt], tid);
            load_chunk(Bg, nrem, ldb, (ch + 1) << 5, boff[nxt], tid);
            cp_commit();
            cp_wait1();
        } else {
            cp_wait0();
        }
        __syncthreads();

        const float* As = sm + cur * ABUF;
        const float* Bs = sm + (2 + cur) * ABUF;

        #pragma unroll
        for (int ks = 0; ks < 4; ks++) {
            int kc = ks << 3;
            uint32_t a[2][4], b[8][2];
            #pragma unroll
            for (int i = 0; i < 2; i++) {
                int r0 = wr * 32 + i * 16 + gid;
                a[i][0] = __float_as_uint(As[(r0)     * ASTRIDE + kc + tig])     + 0x1000u;
                a[i][1] = __float_as_uint(As[(r0 + 8) * ASTRIDE + kc + tig])     + 0x1000u;
                a[i][2] = __float_as_uint(As[(r0)     * ASTRIDE + kc + tig + 4]) + 0x1000u;
                a[i][3] = __float_as_uint(As[(r0 + 8) * ASTRIDE + kc + tig + 4]) + 0x1000u;
            }
            #pragma unroll
            for (int j = 0; j < 8; j++) {
                int nr = wc * 64 + j * 8 + gid;
                b[j][0] = __float_as_uint(Bs[nr * ASTRIDE + kc + tig])     + 0x1000u;
                b[j][1] = __float_as_uint(Bs[nr * ASTRIDE + kc + tig + 4]) + 0x1000u;
            }
            #pragma unroll
            for (int i = 0; i < 2; i++)
                #pragma unroll
                for (int j = 0; j < 8; j++) {
                    asm volatile(
                        "mma.sync.aligned.m16n8k8.row.col.f32.tf32.tf32.f32 "
                        "{%0,%1,%2,%3}, {%4,%5,%6,%7}, {%8,%9}, {%0,%1,%2,%3};"
                        : "+f"(c[i][j][0]), "+f"(c[i][j][1]),
                          "+f"(c[i][j][2]), "+f"(c[i][j][3])
                        : "r"(a[i][0]), "r"(a[i][1]), "r"(a[i][2]), "r"(a[i][3]),
                          "r"(b[j][0]), "r"(b[j][1]));
                }
        }
        __syncthreads();
    }

    // epilogue: scattered stores with bias / gelu
    #pragma unroll
    for (int i = 0; i < 2; i++) {
        int rbase = wr * 32 + i * 16 + gid;
        #pragma unroll
        for (int half = 0; half < 2; half++) {
            int rloc = rbase + half * 8;
            if (rloc >= mrem) continue;
            long long row = m0 + rloc;
            #pragma unroll
            for (int j = 0; j < 8; j++) {
                #pragma unroll
                for (int q = 0; q < 2; q++) {
                    int cloc = wc * 64 + j * 8 + tig * 2 + q;
                    if (cloc >= nrem) continue;
                    int col = n0 + cloc;
                    float v = c[i][j][half * 2 + q];
                    if (bias) v += bias[col];
                    if (act) v = 0.5f * v * (1.f + erff(v * 0.70710678118654752f));
                    C[row * ldcr + (long long)col * ldcc] = v;
                }
            }
        }
    }
}

// ---------------- per-(b,n) stats over S ----------------
__global__ void stats_kernel(const float* __restrict__ x, float* __restrict__ mean,
                             float* __restrict__ stdv)
{
    int bn = blockIdx.x;
    int b = bn / CN, n = bn % CN;
    const float* p = x + (long long)b * CS * CN + n;
    float s = 0.f, s2 = 0.f;
    for (int i = threadIdx.x; i < CS; i += blockDim.x) {
        float v = p[(long long)i * CN];
        s += v; s2 += v * v;
    }
    __shared__ float rs[128], rq[128];
    rs[threadIdx.x] = s; rq[threadIdx.x] = s2; __syncthreads();
    for (int o = 64; o > 0; o >>= 1) {
        if (threadIdx.x < o) { rs[threadIdx.x] += rs[threadIdx.x + o]; rq[threadIdx.x] += rq[threadIdx.x + o]; }
        __syncthreads();
    }
    if (threadIdx.x == 0) {
        float mu = rs[0] / CS;
        float var = rq[0] / CS - mu * mu;
        mean[bn] = mu;
        stdv[bn] = sqrtf(var + 1e-5f);
    }
}

__global__ void norm_t_kernel(const float* __restrict__ x, const float* __restrict__ mean,
                              const float* __restrict__ stdv, float* __restrict__ xt)
{
    long long idx = (long long)blockIdx.x * blockDim.x + threadIdx.x;
    if (idx >= (long long)BND) return;
    int s = (int)(idx & (CS - 1));
    long long bn = idx >> 9;
    int b = (int)(bn / CN), n = (int)(bn % CN);
    xt[idx] = (x[((long long)b * CS + s) * CN + n] - mean[bn]) / stdv[bn];
}

// ---------------- SWT decomposition ----------------
__global__ void swt_dec_kernel(const float* __restrict__ h,
                               const float* __restrict__ f0g, const float* __restrict__ f1g,
                               float* __restrict__ coef)
{
    int bn = blockIdx.x; int n = bn % CN;
    __shared__ float a[CD], b[CD];
    const float* hp = h + (long long)bn * CD;
    for (int d = threadIdx.x; d < CD; d += blockDim.x) a[d] = hp[d];
    float l0[3], l1[3];
    #pragma unroll
    for (int t = 0; t < 3; t++) { l0[t] = f0g[n * 3 + t]; l1[t] = f1g[n * 3 + t]; }
    __syncthreads();
    float* cf = coef + (long long)bn * 4 * CD;
    for (int d = threadIdx.x; d < CD; d += blockDim.x) {
        int im = (d - 1) & 511, ip = (d + 1) & 511;
        cf[3 * CD + d] = l1[0] * a[im] + l1[1] * a[d] + l1[2] * a[ip];
        b[d]           = l0[0] * a[im] + l0[1] * a[d] + l0[2] * a[ip];
    }
    __syncthreads();
    for (int d = threadIdx.x; d < CD; d += blockDim.x) {
        int i0 = (d - 1) & 511, i1 = (d + 1) & 511, i2 = (d + 3) & 511;
        cf[2 * CD + d] = l1[0] * b[i0] + l1[1] * b[i1] + l1[2] * b[i2];
        a[d]           = l0[0] * b[i0] + l0[1] * b[i1] + l0[2] * b[i2];
    }
    __syncthreads();
    for (int d = threadIdx.x; d < CD; d += blockDim.x) {
        int i0 = (d - 2) & 511, i1 = (d + 2) & 511, i2 = (d + 6) & 511;
        cf[1 * CD + d] = l1[0] * a[i0] + l1[1] * a[i1] + l1[2] * a[i2];
        cf[0 * CD + d] = l0[0] * a[i0] + l0[1] * a[i1] + l0[2] * a[i2];
    }
}

// ---------------- SWT reconstruction ----------------
__global__ void swt_rec_kernel(const float* __restrict__ c,
                               const float* __restrict__ g0g, const float* __restrict__ g1g,
                               float* __restrict__ out)
{
    int bn = blockIdx.x; int n = bn % CN;
    const float* cp = c + (long long)bn * 4 * CD;
    __shared__ float a[CD], b[CD], det[CD];
    float f0[3], f1[3];
    #pragma unroll
    for (int t = 0; t < 3; t++) { f0[t] = g0g[n * 3 + t]; f1[t] = g1g[n * 3 + t]; }
    for (int d = threadIdx.x; d < CD; d += blockDim.x) { a[d] = cp[d]; det[d] = cp[CD + d]; }
    __syncthreads();
    for (int d = threadIdx.x; d < CD; d += blockDim.x) {
        int i0 = (d - 6) & 511, i1 = (d - 2) & 511, i2 = (d + 2) & 511;
        b[d] = 0.5f * (f0[0] * a[i0] + f0[1] * a[i1] + f0[2] * a[i2]
                     + f1[0] * det[i0] + f1[1] * det[i1] + f1[2] * det[i2]);
    }
    __syncthreads();
    for (int d = threadIdx.x; d < CD; d += blockDim.x) det[d] = cp[2 * CD + d];
    __syncthreads();
    for (int d = threadIdx.x; d < CD; d += blockDim.x) {
        int i0 = (d - 3) & 511, i1 = (d - 1) & 511, i2 = (d + 1) & 511;
        a[d] = 0.5f * (f0[0] * b[i0] + f0[1] * b[i1] + f0[2] * b[i2]
                     + f1[0] * det[i0] + f1[1] * det[i1] + f1[2] * det[i2]);
    }
    __syncthreads();
    for (int d = threadIdx.x; d < CD; d += blockDim.x) det[d] = cp[3 * CD + d];
    __syncthreads();
    float* op = out + (long long)bn * CD;
    for (int d = threadIdx.x; d < CD; d += blockDim.x) {
        int i0 = (d - 1) & 511, i2 = (d + 1) & 511;
        op[d] = 0.5f * (f0[0] * a[i0] + f0[1] * a[d] + f0[2] * a[i2]
                      + f1[0] * det[i0] + f1[1] * det[d] + f1[2] * det[i2]);
    }
}

// ---------------- transpose [b][n][m][e] -> [b][m][e][KPAD] (zero-padded) ----------------
__global__ void trans_kernel(const float* __restrict__ in, float* __restrict__ out)
{
    int z = blockIdx.z; int b = z >> 2, m = z & 3;
    __shared__ float t[32][33];
    int e0 = blockIdx.x * 32, n0 = blockIdx.y * 32;
    int tx = threadIdx.x, ty = threadIdx.y;
    #pragma unroll
    for (int j = 0; j < 4; j++) {
        int e = e0 + tx, n = n0 + ty + j * 8;
        t[ty + j * 8][tx] = (n < CN) ? in[(((long long)b * CN + n) * 4 + m) * CD + e] : 0.f;
    }
    __syncthreads();
    #pragma unroll
    for (int j = 0; j < 4; j++) {
        int n = n0 + tx, e = e0 + ty + j * 8;
        out[(((long long)b * 4 + m) * CD + e) * KPAD + n] = t[tx][ty + j * 8];
    }
}

// ---------------- row squared-norm (rows of length CN, stride KPAD) ----------------
__global__ void rowsq_kernel(const float* __restrict__ in, float* __restrict__ out)
{
    int r = blockIdx.x;
    const float* p = in + (long long)r * KPAD;
    float s = 0.f;
    for (int i = threadIdx.x; i < CN; i += blockDim.x) { float v = p[i]; s += v * v; }
    __shared__ float rs[128];
    rs[threadIdx.x] = s; __syncthreads();
    for (int o = 64; o > 0; o >>= 1) {
        if (threadIdx.x < o) rs[threadIdx.x] += rs[threadIdx.x + o];
        __syncthreads();
    }
    if (threadIdx.x == 0) out[r] = rs[0];
}

// ---------------- wedge score + softmax (in place on dot) ----------------
__global__ void score_softmax_kernel(float* __restrict__ dot,
                                     const float* __restrict__ qn2,
                                     const float* __restrict__ kn2)
{
    int row = blockIdx.x;
    int z = row >> 9;
    float q2 = qn2[row];
    float* p = dot + (long long)row * CD;
    const float* k2 = kn2 + (long long)z * CD;
    const float scale = 1.f / sqrtf((float)CN);
    int t = threadIdx.x;
    float sc[2];
    float mx = -1e30f;
    #pragma unroll
    for (int j = 0; j < 2; j++) {
        int s = t + j * 256;
        float d = p[s];
        float w = sqrtf(fmaxf(q2 * k2[s] - d * d, 0.f) + 1e-8f);
        float v = ((1.f - ALPHA_) * d + ALPHA_ * w) * scale;
        sc[j] = v;
        mx = fmaxf(mx, v);
    }
    __shared__ float red[256];
    red[t] = mx; __syncthreads();
    for (int o = 128; o > 0; o >>= 1) {
        if (t < o) red[t] = fmaxf(red[t], red[t + o]);
        __syncthreads();
    }
    mx = red[0]; __syncthreads();
    float sum = 0.f;
    #pragma unroll
    for (int j = 0; j < 2; j++) { sc[j] = expf(sc[j] - mx); sum += sc[j]; }
    red[t] = sum; __syncthreads();
    for (int o = 128; o > 0; o >>= 1) {
        if (t < o) red[t] += red[t + o];
        __syncthreads();
    }
    float inv = 1.f / red[0];
    #pragma unroll
    for (int j = 0; j < 2; j++) p[t + j * 256] = sc[j] * inv;
}

// ---------------- add + layernorm ----------------
__global__ void add_ln_kernel(const float* __restrict__ x, const float* __restrict__ y,
                              const float* __restrict__ g, const float* __restrict__ bb,
                              float* __restrict__ out)
{
    int bn = blockIdx.x;
    const float* xp = x + (long long)bn * CD;
    const float* yp = y ? y + (long long)bn * CD : nullptr;
    int t = threadIdx.x;
    float v[2];
    float s = 0.f;
    #pragma unroll
    for (int j = 0; j < 2; j++) {
        int d = t + j * 256;
        v[j] = xp[d] + (yp ? yp[d] : 0.f);
        s += v[j];
    }
    __shared__ float red[256];
    red[t] = s; __syncthreads();
    for (int o = 128; o > 0; o >>= 1) { if (t < o) red[t] += red[t + o]; __syncthreads(); }
    float mu = red[0] / CD; __syncthreads();
    float s2 = 0.f;
    #pragma unroll
    for (int j = 0; j < 2; j++) { float dv = v[j] - mu; s2 += dv * dv; }
    red[t] = s2; __syncthreads();
    for (int o = 128; o > 0; o >>= 1) { if (t < o) red[t] += red[t + o]; __syncthreads(); }
    float inv = 1.f / sqrtf(red[0] / CD + 1e-5f);
    #pragma unroll
    for (int j = 0; j < 2; j++) {
        int d = t + j * 256;
        out[(long long)bn * CD + d] = (v[j] - mu) * inv * g[d] + bb[d];
    }
}

// ---------------- final output de-normalization ----------------
__global__ void out_kernel(const float* __restrict__ dec, const float* __restrict__ mean,
                           const float* __restrict__ stdv, float* __restrict__ out)
{
    int idx = blockIdx.x * blockDim.x + threadIdx.x;
    if (idx >= CB * CP * CN) return;
    int n = idx % CN;
    int p = (idx / CN) % CP;
    int b = idx / (CN * CP);
    int bn = b * CN + n;
    out[idx] = dec[(long long)bn * CP + p] * stdv[bn] + mean[bn];
}

__global__ void aux_out_kernel(const float* __restrict__ mean, const float* __restrict__ stdv,
                               float* __restrict__ out)
{
    int i = blockIdx.x * blockDim.x + threadIdx.x;
    if (i >= CBN) return;
    out[CB * CP * CN + i] = mean[i];
    out[CB * CP * CN + CBN + i] = stdv[i];
}

// ---------------- host orchestration ----------------
static void launch_tc(const float* A, const float* B, float* C, const float* bias,
                      int M, int Nn, int Kd, int lda, int ldb,
                      long long ldcr, long long ldcc,
                      int batches, int bdiv,
                      long long sAh, long long sAl,
                      long long sBh, long long sBl,
                      long long sCh, long long sCl, int act)
{
    dim3 grid((M + 127) / 128, (Nn + 127) / 128, batches);
    gemm_tc<<<grid, 256, SMEM_DYN>>>(A, B, C, bias, M, Nn, Kd, lda, ldb, ldcr, ldcc,
                                     bdiv, sAh, sAl, sBh, sBl, sCh, sCl, act);
}

extern "C" void kernel_launch(void* const* d_in, const int* in_sizes, int n_in,
                              void* d_out, int out_size)
{
    (void)in_sizes; (void)n_in;
    const float* x_enc  = (const float*)d_in[0];
    const float* emb_W  = (const float*)d_in[1];
    const float* emb_b  = (const float*)d_in[2];
    const float* h0     = (const float*)d_in[3];
    const float* h1     = (const float*)d_in[4];
    const float* g0     = (const float*)d_in[5];
    const float* g1     = (const float*)d_in[6];
    const float* Wq     = (const float*)d_in[7];
    const float* bq     = (const float*)d_in[8];
    const float* Wk     = (const float*)d_in[9];
    const float* bk     = (const float*)d_in[10];
    const float* Wv     = (const float*)d_in[11];
    const float* bv     = (const float*)d_in[12];
    const float* Wo     = (const float*)d_in[13];
    const float* bo     = (const float*)d_in[14];
    const float* W1     = (const float*)d_in[15];
    const float* b1     = (const float*)d_in[16];
    const float* W2     = (const float*)d_in[17];
    const float* b2     = (const float*)d_in[18];
    const float* ln1_g  = (const float*)d_in[19];
    const float* ln1_b  = (const float*)d_in[20];
    const float* ln2_g  = (const float*)d_in[21];
    const float* ln2_b  = (const float*)d_in[22];
    const float* lnf_g  = (const float*)d_in[23];
    const float* lnf_b  = (const float*)d_in[24];
    const float* proj_W = (const float*)d_in[25];
    const float* proj_b = (const float*)d_in[26];

    cudaFuncSetAttribute(gemm_tc, cudaFuncAttributeMaxDynamicSharedMemorySize, SMEM_DYN);

    float* ws = nullptr;
    cudaGetSymbolAddress((void**)&ws, g_ws);

    float* xt   = ws + O_XT;
    float* h    = ws + O_H;
    float* mean = ws + O_MEAN;
    float* stdv = ws + O_STD;
    float* coef = ws + O_COEF;
    float* q    = ws + O_Q;
    float* k    = ws + O_K;
    float* v    = ws + O_V;
    float* qa   = ws + O_QA;
    float* ka   = ws + O_KA;
    float* dot  = ws + O_DOT;
    float* qn2  = ws + O_QN2;
    float* kn2  = ws + O_KN2;
    float* ao   = ws + O_AO;
    float* rec  = ws + O_REC;
    float* att  = ws + O_ATT;
    float* x1   = ws + O_X1;
    float* ff   = ws + O_FF;
    float* y2   = ws + O_Y2;
    float* dec  = ws + O_DEC;

    stats_kernel<<<CBN, 128>>>(x_enc, mean, stdv);
    norm_t_kernel<<<(int)((BND + 255) / 256), 256>>>(x_enc, mean, stdv, xt);

    // embedding
    launch_tc(xt, emb_W, h, emb_b, CBN, CD, CS, CS, CS, CD, 1,
              1, 1, 0, 0, 0, 0, 0, 0, 0);

    const long long ZAP = (long long)CD * KPAD;
    const long long ZD  = (long long)CD * CD;
    const long long BSTR = (long long)CN * 4 * CD;

    for (int l = 0; l < 2; l++) {
        swt_dec_kernel<<<CBN, 256>>>(h, h0 + (long long)l * CN * 3, h1 + (long long)l * CN * 3, coef);

        launch_tc(coef, Wq + (long long)l * CD * CD, q, bq + (long long)l * CD,
                  CBN * 4, CD, CD, CD, CD, CD, 1, 1, 1, 0, 0, 0, 0, 0, 0, 0);
        launch_tc(coef, Wk + (long long)l * CD * CD, k, bk + (long long)l * CD,
                  CBN * 4, CD, CD, CD, CD, CD, 1, 1, 1, 0, 0, 0, 0, 0, 0, 0);
        launch_tc(coef, Wv + (long long)l * CD * CD, v, bv + (long long)l * CD,
                  CBN * 4, CD, CD, CD, CD, CD, 1, 1, 1, 0, 0, 0, 0, 0, 0, 0);

        {
            dim3 g2(16, KPAD / 32, CB * 4), b2d(32, 8);
            trans_kernel<<<g2, b2d>>>(q, qa);
            trans_kernel<<<g2, b2d>>>(k, ka);
        }
        rowsq_kernel<<<CB * 4 * CD, 128>>>(qa, qn2);
        rowsq_kernel<<<CB * 4 * CD, 128>>>(ka, kn2);

        // QK^T batched over z = b*4+m (K zero-padded to KPAD)
        launch_tc(qa, ka, dot, nullptr, CD, CD, KPAD, KPAD, KPAD, CD, 1,
                  CB * 4, 1, ZAP, 0, ZAP, 0, ZD, 0, 0);

        score_softmax_kernel<<<CB * 4 * CD, 256>>>(dot, qn2, kn2);

        // AV with scatter back into coeffs layout [b][n][m][l]
        launch_tc(dot, v, ao, nullptr, CD, CN, CD, CD, 4 * CD, 1, 4 * CD,
                  CB * 4, 4,
                  4 * ZD, ZD,
                  BSTR, CD,
                  BSTR, CD,
                  0);

        swt_rec_kernel<<<CBN, 256>>>(ao, g0 + (long long)l * CN * 3, g1 + (long long)l * CN * 3, rec);

        launch_tc(rec, Wo + (long long)l * CD * CD, att, bo + (long long)l * CD,
                  CBN, CD, CD, CD, CD, CD, 1, 1, 1, 0, 0, 0, 0, 0, 0, 0);

        add_ln_kernel<<<CBN, 256>>>(h, att, ln1_g + (long long)l * CD, ln1_b + (long long)l * CD, x1);

        launch_tc(x1, W1 + (long long)l * CDF * CD, ff, b1 + (long long)l * CDF,
                  CBN, CDF, CD, CD, CD, CDF, 1, 1, 1, 0, 0, 0, 0, 0, 0, 1);
        launch_tc(ff, W2 + (long long)l * CD * CDF, y2, b2 + (long long)l * CD,
                  CBN, CD, CDF, CDF, CDF, CD, 1, 1, 1, 0, 0, 0, 0, 0, 0, 0);

        add_ln_kernel<<<CBN, 256>>>(x1, y2, ln2_g + (long long)l * CD, ln2_b + (long long)l * CD, h);
    }

    add_ln_kernel<<<CBN, 256>>>(h, nullptr, lnf_g, lnf_b, x1);
    launch_tc(x1, proj_W, dec, proj_b, CBN, CP, CD, CD, CD, CP, 1,
              1, 1, 0, 0, 0, 0, 0, 0, 0);

    out_kernel<<<(CB * CP * CN + 255) / 256, 256>>>(dec, mean, stdv, (float*)d_out);
    if (out_size >= CB * CP * CN + 2 * CBN) {
        aux_out_kernel<<<(CBN + 255) / 256, 256>>>(mean, stdv, (float*)d_out);
    }
}

// round 6
// speedup vs baseline: 6.0413x; 1.3451x over previous
#include <cuda_runtime.h>
#include <cuda_fp16.h>
#include <math.h>
#include <stdint.h>

#define CB 16
#define CS 512
#define CN 321
#define CD 512
#define CDF 2048
#define CP 96
#define KPAD 352
#define CBN (CB*CN)
#define BND ((size_t)CBN*CD)
#define BNMD ((size_t)CBN*4*CD)
#define QAPAD ((size_t)CB*4*CD*KPAD)
#define ATT ((size_t)CB*4*CD*CD)
#define ALPHA_ 0.3f

// ---------------- fp32 workspace ----------------
#define O_H    ((size_t)0)
#define O_MEAN (O_H + BND)
#define O_STD  (O_MEAN + CBN)
#define O_DOT  (O_STD + CBN)
#define O_AO   (O_DOT + ATT)
#define O_ATT  (O_AO + BNMD)
#define O_X1   (O_ATT + BND)
#define O_Y2   (O_X1 + BND)
#define O_DEC  (O_Y2 + BND)
#define WS_TOTAL (O_DEC + (size_t)CBN*CP)
__device__ float g_ws[WS_TOTAL];

// ---------------- fp16 workspace ----------------
#define H_XT   ((size_t)0)
#define H_COEF (H_XT + BND)
#define H_Q    (H_COEF + BNMD)
#define H_K    (H_Q + BNMD)
#define H_V    (H_K + BNMD)
#define H_QA   (H_V + BNMD)
#define H_KA   (H_QA + QAPAD)
#define H_PROB (H_KA + QAPAD)
#define H_REC  (H_PROB + ATT)
#define H_X1   (H_REC + BND)
#define H_FF   (H_X1 + BND)
#define H_EMBW (H_FF + (size_t)CBN*CDF)
#define H_WQ   (H_EMBW + (size_t)CD*CS)
#define H_WK   (H_WQ + (size_t)2*CD*CD)
#define H_WV   (H_WK + (size_t)2*CD*CD)
#define H_WO   (H_WV + (size_t)2*CD*CD)
#define H_W1   (H_WO + (size_t)2*CD*CD)
#define H_W2   (H_W1 + (size_t)2*CDF*CD)
#define H_PW   (H_W2 + (size_t)2*CDF*CD)
#define HW_TOTAL (H_PW + (size_t)CP*CD)
__device__ __align__(16) __half g_hws[HW_TOTAL];

// ---------------- helpers ----------------
__device__ __forceinline__ uint32_t smem_u32(const void* p) {
    uint32_t a;
    asm("{ .reg .u64 t; cvta.to.shared.u64 t, %1; cvt.u32.u64 %0, t; }" : "=r"(a) : "l"(p));
    return a;
}
__device__ __forceinline__ void cp16(uint32_t dst, const void* src, int sz) {
    asm volatile("cp.async.cg.shared.global [%0], [%1], 16, %2;"
                 :: "r"(dst), "l"(src), "r"(sz));
}
__device__ __forceinline__ void cp_commit() { asm volatile("cp.async.commit_group;" ::: "memory"); }
__device__ __forceinline__ void cp_wait1()  { asm volatile("cp.async.wait_group 1;" ::: "memory"); }
__device__ __forceinline__ void cp_wait0()  { asm volatile("cp.async.wait_group 0;" ::: "memory"); }

#define ASTRIDE 40                    /* halves; 80B row pitch -> conflict-free & 16B aligned */
#define ABUF (128*ASTRIDE)            /* halves per buffer */
#define ABUF_B (ABUF*2)               /* bytes */
#define SMEM_DYN (4*ABUF_B)           /* 40960 bytes */

// async load 128 rows x 32 halves of a K-chunk, zero-pad OOB rows
__device__ __forceinline__ void load_chunk(const __half* __restrict__ g, int rows, int ld,
                                           int k0, uint32_t smbase, int tid) {
    #pragma unroll
    for (int i = 0; i < 2; i++) {
        int idx = tid + (i << 8);
        int r = idx >> 2, c = idx & 3;
        int ok = r < rows;
        const __half* src = g + (long long)(ok ? r : 0) * ld + k0 + c * 8;
        cp16(smbase + (uint32_t)(r * ASTRIDE + c * 8) * 2u, src, ok ? 16 : 0);
    }
}

// ============ generic batched NT GEMM via mma.sync fp16 (fp32 accum) ============
// C[row,col] = sum_k A[row,k]*B[col,k] (+bias[col])
// act bit0 = gelu, bit1 = fp16 output (C interpreted as __half*)
__global__ __launch_bounds__(256, 2) void gemm_tc(
    const __half* __restrict__ A, const __half* __restrict__ Bm,
    float* __restrict__ C, const float* __restrict__ bias,
    int M, int Nn, int Kd, int lda, int ldb,
    long long ldcr, long long ldcc, int bdiv,
    long long sAh, long long sAl, long long sBh, long long sBl,
    long long sCh, long long sCl, int act)
{
    extern __shared__ __half smh[];
    const int tid = threadIdx.x;
    const int wid = tid >> 5, lane = tid & 31;
    const int gid = lane >> 2, tig = lane & 3;
    const int wr = wid & 3, wc = wid >> 2;

    int z = blockIdx.z;
    int zh = z / bdiv, zl = z % bdiv;
    A  += zh * sAh + zl * sAl;
    Bm += zh * sBh + zl * sBl;

    long long coff = zh * sCh + zl * sCl;

    int m0 = blockIdx.x * 128, n0 = blockIdx.y * 128;
    int mrem = M - m0, nrem = Nn - n0;
    const __half* Ag = A + (long long)m0 * lda;
    const __half* Bg = Bm + (long long)n0 * ldb;

    uint32_t smb = smem_u32(smh);
    const uint32_t aoff[2] = { smb, smb + ABUF_B };
    const uint32_t boff[2] = { smb + 2 * ABUF_B, smb + 3 * ABUF_B };

    float c[2][8][4];
    #pragma unroll
    for (int i = 0; i < 2; i++)
        #pragma unroll
        for (int j = 0; j < 8; j++)
            #pragma unroll
            for (int r = 0; r < 4; r++) c[i][j][r] = 0.f;

    const int NC = Kd >> 5;
    load_chunk(Ag, mrem, lda, 0, aoff[0], tid);
    load_chunk(Bg, nrem, ldb, 0, boff[0], tid);
    cp_commit();

    for (int ch = 0; ch < NC; ch++) {
        int cur = ch & 1;
        if (ch + 1 < NC) {
            int nxt = cur ^ 1;
            load_chunk(Ag, mrem, lda, (ch + 1) << 5, aoff[nxt], tid);
            load_chunk(Bg, nrem, ldb, (ch + 1) << 5, boff[nxt], tid);
            cp_commit();
            cp_wait1();
        } else {
            cp_wait0();
        }
        __syncthreads();

        const __half* As = smh + cur * ABUF;
        const __half* Bs = smh + (2 + cur) * ABUF;

        #pragma unroll
        for (int ks = 0; ks < 2; ks++) {
            int kc = ks << 4;
            uint32_t a[2][4], b[8][2];
            #pragma unroll
            for (int i = 0; i < 2; i++) {
                int r0 = wr * 32 + i * 16 + gid;
                a[i][0] = *(const uint32_t*)(As + (r0)     * ASTRIDE + kc + tig * 2);
                a[i][1] = *(const uint32_t*)(As + (r0 + 8) * ASTRIDE + kc + tig * 2);
                a[i][2] = *(const uint32_t*)(As + (r0)     * ASTRIDE + kc + tig * 2 + 8);
                a[i][3] = *(const uint32_t*)(As + (r0 + 8) * ASTRIDE + kc + tig * 2 + 8);
            }
            #pragma unroll
            for (int j = 0; j < 8; j++) {
                int nr = wc * 64 + j * 8 + gid;
                b[j][0] = *(const uint32_t*)(Bs + nr * ASTRIDE + kc + tig * 2);
                b[j][1] = *(const uint32_t*)(Bs + nr * ASTRIDE + kc + tig * 2 + 8);
            }
            #pragma unroll
            for (int i = 0; i < 2; i++)
                #pragma unroll
                for (int j = 0; j < 8; j++) {
                    asm volatile(
                        "mma.sync.aligned.m16n8k16.row.col.f32.f16.f16.f32 "
                        "{%0,%1,%2,%3}, {%4,%5,%6,%7}, {%8,%9}, {%0,%1,%2,%3};"
                        : "+f"(c[i][j][0]), "+f"(c[i][j][1]),
                          "+f"(c[i][j][2]), "+f"(c[i][j][3])
                        : "r"(a[i][0]), "r"(a[i][1]), "r"(a[i][2]), "r"(a[i][3]),
                          "r"(b[j][0]), "r"(b[j][1]));
                }
        }
        __syncthreads();
    }

    // epilogue
    #pragma unroll
    for (int i = 0; i < 2; i++) {
        int rbase = wr * 32 + i * 16 + gid;
        #pragma unroll
        for (int half = 0; half < 2; half++) {
            int rloc = rbase + half * 8;
            if (rloc >= mrem) continue;
            long long row = m0 + rloc;
            #pragma unroll
            for (int j = 0; j < 8; j++) {
                #pragma unroll
                for (int q = 0; q < 2; q++) {
                    int cloc = wc * 64 + j * 8 + tig * 2 + q;
                    if (cloc >= nrem) continue;
                    int col = n0 + cloc;
                    float v = c[i][j][half * 2 + q];
                    if (bias) v += bias[col];
                    if (act & 1) v = 0.5f * v * (1.f + erff(v * 0.70710678118654752f));
                    long long off = coff + row * ldcr + (long long)col * ldcc;
                    if (act & 2) ((__half*)C)[off] = __float2half(v);
                    else C[off] = v;
                }
            }
        }
    }
}

// ---------------- f32 -> f16 conversion ----------------
__global__ void f2h_kernel(const float* __restrict__ in, __half* __restrict__ out, long long n)
{
    long long i = (long long)blockIdx.x * blockDim.x + threadIdx.x;
    if (i < n) out[i] = __float2half(in[i]);
}

// ---------------- per-(b,n) stats over S ----------------
__global__ void stats_kernel(const float* __restrict__ x, float* __restrict__ mean,
                             float* __restrict__ stdv)
{
    int bn = blockIdx.x;
    int b = bn / CN, n = bn % CN;
    const float* p = x + (long long)b * CS * CN + n;
    float s = 0.f, s2 = 0.f;
    for (int i = threadIdx.x; i < CS; i += blockDim.x) {
        float v = p[(long long)i * CN];
        s += v; s2 += v * v;
    }
    __shared__ float rs[128], rq[128];
    rs[threadIdx.x] = s; rq[threadIdx.x] = s2; __syncthreads();
    for (int o = 64; o > 0; o >>= 1) {
        if (threadIdx.x < o) { rs[threadIdx.x] += rs[threadIdx.x + o]; rq[threadIdx.x] += rq[threadIdx.x + o]; }
        __syncthreads();
    }
    if (threadIdx.x == 0) {
        float mu = rs[0] / CS;
        float var = rq[0] / CS - mu * mu;
        mean[bn] = mu;
        stdv[bn] = sqrtf(var + 1e-5f);
    }
}

// xt_h[(b,n),s] = fp16((x[b,s,n]-mean)/std)
__global__ void norm_t_kernel(const float* __restrict__ x, const float* __restrict__ mean,
                              const float* __restrict__ stdv, __half* __restrict__ xt)
{
    long long idx = (long long)blockIdx.x * blockDim.x + threadIdx.x;
    if (idx >= (long long)BND) return;
    int s = (int)(idx & (CS - 1));
    long long bn = idx >> 9;
    int b = (int)(bn / CN), n = (int)(bn % CN);
    xt[idx] = __float2half((x[((long long)b * CS + s) * CN + n] - mean[bn]) / stdv[bn]);
}

// ---------------- SWT decomposition (fp32 in, fp16 out) ----------------
__global__ void swt_dec_kernel(const float* __restrict__ h,
                               const float* __restrict__ f0g, const float* __restrict__ f1g,
                               __half* __restrict__ coef)
{
    int bn = blockIdx.x; int n = bn % CN;
    __shared__ float a[CD], b[CD];
    const float* hp = h + (long long)bn * CD;
    for (int d = threadIdx.x; d < CD; d += blockDim.x) a[d] = hp[d];
    float l0[3], l1[3];
    #pragma unroll
    for (int t = 0; t < 3; t++) { l0[t] = f0g[n * 3 + t]; l1[t] = f1g[n * 3 + t]; }
    __syncthreads();
    __half* cf = coef + (long long)bn * 4 * CD;
    for (int d = threadIdx.x; d < CD; d += blockDim.x) {
        int im = (d - 1) & 511, ip = (d + 1) & 511;
        cf[3 * CD + d] = __float2half(l1[0] * a[im] + l1[1] * a[d] + l1[2] * a[ip]);
        b[d]           = l0[0] * a[im] + l0[1] * a[d] + l0[2] * a[ip];
    }
    __syncthreads();
    for (int d = threadIdx.x; d < CD; d += blockDim.x) {
        int i0 = (d - 1) & 511, i1 = (d + 1) & 511, i2 = (d + 3) & 511;
        cf[2 * CD + d] = __float2half(l1[0] * b[i0] + l1[1] * b[i1] + l1[2] * b[i2]);
        a[d]           = l0[0] * b[i0] + l0[1] * b[i1] + l0[2] * b[i2];
    }
    __syncthreads();
    for (int d = threadIdx.x; d < CD; d += blockDim.x) {
        int i0 = (d - 2) & 511, i1 = (d + 2) & 511, i2 = (d + 6) & 511;
        cf[1 * CD + d] = __float2half(l1[0] * a[i0] + l1[1] * a[i1] + l1[2] * a[i2]);
        cf[0 * CD + d] = __float2half(l0[0] * a[i0] + l0[1] * a[i1] + l0[2] * a[i2]);
    }
}

// ---------------- SWT reconstruction (fp32 in, fp16 out) ----------------
__global__ void swt_rec_kernel(const float* __restrict__ c,
                               const float* __restrict__ g0g, const float* __restrict__ g1g,
                               __half* __restrict__ out)
{
    int bn = blockIdx.x; int n = bn % CN;
    const float* cp = c + (long long)bn * 4 * CD;
    __shared__ float a[CD], b[CD], det[CD];
    float f0[3], f1[3];
    #pragma unroll
    for (int t = 0; t < 3; t++) { f0[t] = g0g[n * 3 + t]; f1[t] = g1g[n * 3 + t]; }
    for (int d = threadIdx.x; d < CD; d += blockDim.x) { a[d] = cp[d]; det[d] = cp[CD + d]; }
    __syncthreads();
    for (int d = threadIdx.x; d < CD; d += blockDim.x) {
        int i0 = (d - 6) & 511, i1 = (d - 2) & 511, i2 = (d + 2) & 511;
        b[d] = 0.5f * (f0[0] * a[i0] + f0[1] * a[i1] + f0[2] * a[i2]
                     + f1[0] * det[i0] + f1[1] * det[i1] + f1[2] * det[i2]);
    }
    __syncthreads();
    for (int d = threadIdx.x; d < CD; d += blockDim.x) det[d] = cp[2 * CD + d];
    __syncthreads();
    for (int d = threadIdx.x; d < CD; d += blockDim.x) {
        int i0 = (d - 3) & 511, i1 = (d - 1) & 511, i2 = (d + 1) & 511;
        a[d] = 0.5f * (f0[0] * b[i0] + f0[1] * b[i1] + f0[2] * b[i2]
                     + f1[0] * det[i0] + f1[1] * det[i1] + f1[2] * det[i2]);
    }
    __syncthreads();
    for (int d = threadIdx.x; d < CD; d += blockDim.x) det[d] = cp[3 * CD + d];
    __syncthreads();
    __half* op = out + (long long)bn * CD;
    for (int d = threadIdx.x; d < CD; d += blockDim.x) {
        int i0 = (d - 1) & 511, i2 = (d + 1) & 511;
        op[d] = __float2half(0.5f * (f0[0] * a[i0] + f0[1] * a[d] + f0[2] * a[i2]
                                   + f1[0] * det[i0] + f1[1] * det[d] + f1[2] * det[i2]));
    }
}

// ---------------- transpose fp16 [b][n][m][e] -> [b][m][e][KPAD] ----------------
__global__ void trans_kernel(const __half* __restrict__ in, __half* __restrict__ out)
{
    int z = blockIdx.z; int b = z >> 2, m = z & 3;
    __shared__ __half t[32][34];
    int e0 = blockIdx.x * 32, n0 = blockIdx.y * 32;
    int tx = threadIdx.x, ty = threadIdx.y;
    #pragma unroll
    for (int j = 0; j < 4; j++) {
        int e = e0 + tx, n = n0 + ty + j * 8;
        t[ty + j * 8][tx] = (n < CN) ? in[(((long long)b * CN + n) * 4 + m) * CD + e]
                                     : __float2half(0.f);
    }
    __syncthreads();
    #pragma unroll
    for (int j = 0; j < 4; j++) {
        int n = n0 + tx, e = e0 + ty + j * 8;
        out[(((long long)b * 4 + m) * CD + e) * KPAD + n] = t[tx][ty + j * 8];
    }
}

// ---------------- row squared-norm (fp16 rows of length CN, stride KPAD) ----------------
__global__ void rowsq_kernel(const __half* __restrict__ in, float* __restrict__ out)
{
    int r = blockIdx.x;
    const __half* p = in + (long long)r * KPAD;
    float s = 0.f;
    for (int i = threadIdx.x; i < CN; i += blockDim.x) { float v = __half2float(p[i]); s += v * v; }
    __shared__ float rs[128];
    rs[threadIdx.x] = s; __syncthreads();
    for (int o = 64; o > 0; o >>= 1) {
        if (threadIdx.x < o) rs[threadIdx.x] += rs[threadIdx.x + o];
        __syncthreads();
    }
    if (threadIdx.x == 0) out[r] = rs[0];
}

// ---------------- wedge score + softmax (fp32 in, fp16 probs out) ----------------
__global__ void score_softmax_kernel(const float* __restrict__ dot,
                                     const float* __restrict__ qn2,
                                     const float* __restrict__ kn2,
                                     __half* __restrict__ prob)
{
    int row = blockIdx.x;
    int z = row >> 9;
    float q2 = qn2[row];
    const float* p = dot + (long long)row * CD;
    __half* pr = prob + (long long)row * CD;
    const float* k2 = kn2 + (long long)z * CD;
    const float scale = 1.f / sqrtf((float)CN);
    int t = threadIdx.x;
    float sc[2];
    float mx = -1e30f;
    #pragma unroll
    for (int j = 0; j < 2; j++) {
        int s = t + j * 256;
        float d = p[s];
        float w = sqrtf(fmaxf(q2 * k2[s] - d * d, 0.f) + 1e-8f);
        float v = ((1.f - ALPHA_) * d + ALPHA_ * w) * scale;
        sc[j] = v;
        mx = fmaxf(mx, v);
    }
    __shared__ float red[256];
    red[t] = mx; __syncthreads();
    for (int o = 128; o > 0; o >>= 1) {
        if (t < o) red[t] = fmaxf(red[t], red[t + o]);
        __syncthreads();
    }
    mx = red[0]; __syncthreads();
    float sum = 0.f;
    #pragma unroll
    for (int j = 0; j < 2; j++) { sc[j] = expf(sc[j] - mx); sum += sc[j]; }
    red[t] = sum; __syncthreads();
    for (int o = 128; o > 0; o >>= 1) {
        if (t < o) red[t] += red[t + o];
        __syncthreads();
    }
    float inv = 1.f / red[0];
    #pragma unroll
    for (int j = 0; j < 2; j++) pr[t + j * 256] = __float2half(sc[j] * inv);
}

// ---------------- add + layernorm (fp32 out + optional fp16 out) ----------------
__global__ void add_ln_kernel(const float* __restrict__ x, const float* __restrict__ y,
                              const float* __restrict__ g, const float* __restrict__ bb,
                              float* __restrict__ out, __half* __restrict__ outh)
{
    int bn = blockIdx.x;
    const float* xp = x + (long long)bn * CD;
    const float* yp = y ? y + (long long)bn * CD : nullptr;
    int t = threadIdx.x;
    float v[2];
    float s = 0.f;
    #pragma unroll
    for (int j = 0; j < 2; j++) {
        int d = t + j * 256;
        v[j] = xp[d] + (yp ? yp[d] : 0.f);
        s += v[j];
    }
    __shared__ float red[256];
    red[t] = s; __syncthreads();
    for (int o = 128; o > 0; o >>= 1) { if (t < o) red[t] += red[t + o]; __syncthreads(); }
    float mu = red[0] / CD; __syncthreads();
    float s2 = 0.f;
    #pragma unroll
    for (int j = 0; j < 2; j++) { float dv = v[j] - mu; s2 += dv * dv; }
    red[t] = s2; __syncthreads();
    for (int o = 128; o > 0; o >>= 1) { if (t < o) red[t] += red[t + o]; __syncthreads(); }
    float inv = 1.f / sqrtf(red[0] / CD + 1e-5f);
    #pragma unroll
    for (int j = 0; j < 2; j++) {
        int d = t + j * 256;
        float r = (v[j] - mu) * inv * g[d] + bb[d];
        if (out)  out[(long long)bn * CD + d] = r;
        if (outh) outh[(long long)bn * CD + d] = __float2half(r);
    }
}

// ---------------- final output de-normalization ----------------
__global__ void out_kernel(const float* __restrict__ dec, const float* __restrict__ mean,
                           const float* __restrict__ stdv, float* __restrict__ out)
{
    int idx = blockIdx.x * blockDim.x + threadIdx.x;
    if (idx >= CB * CP * CN) return;
    int n = idx % CN;
    int p = (idx / CN) % CP;
    int b = idx / (CN * CP);
    int bn = b * CN + n;
    out[idx] = dec[(long long)bn * CP + p] * stdv[bn] + mean[bn];
}

__global__ void aux_out_kernel(const float* __restrict__ mean, const float* __restrict__ stdv,
                               float* __restrict__ out)
{
    int i = blockIdx.x * blockDim.x + threadIdx.x;
    if (i >= CBN) return;
    out[CB * CP * CN + i] = mean[i];
    out[CB * CP * CN + CBN + i] = stdv[i];
}

// ---------------- host orchestration ----------------
static void launch_tc(const __half* A, const __half* B, float* C, const float* bias,
                      int M, int Nn, int Kd, int lda, int ldb,
                      long long ldcr, long long ldcc,
                      int batches, int bdiv,
                      long long sAh, long long sAl,
                      long long sBh, long long sBl,
                      long long sCh, long long sCl, int act)
{
    dim3 grid((M + 127) / 128, (Nn + 127) / 128, batches);
    gemm_tc<<<grid, 256, SMEM_DYN>>>(A, B, C, bias, M, Nn, Kd, lda, ldb, ldcr, ldcc,
                                     bdiv, sAh, sAl, sBh, sBl, sCh, sCl, act);
}

static void f2h(const float* in, __half* out, long long n)
{
    f2h_kernel<<<(int)((n + 255) / 256), 256>>>(in, out, n);
}

extern "C" void kernel_launch(void* const* d_in, const int* in_sizes, int n_in,
                              void* d_out, int out_size)
{
    (void)in_sizes; (void)n_in;
    const float* x_enc  = (const float*)d_in[0];
    const float* emb_W  = (const float*)d_in[1];
    const float* emb_b  = (const float*)d_in[2];
    const float* h0     = (const float*)d_in[3];
    const float* h1     = (const float*)d_in[4];
    const float* g0     = (const float*)d_in[5];
    const float* g1     = (const float*)d_in[6];
    const float* Wq     = (const float*)d_in[7];
    const float* bq     = (const float*)d_in[8];
    const float* Wk     = (const float*)d_in[9];
    const float* bk     = (const float*)d_in[10];
    const float* Wv     = (const float*)d_in[11];
    const float* bv     = (const float*)d_in[12];
    const float* Wo     = (const float*)d_in[13];
    const float* bo     = (const float*)d_in[14];
    const float* W1     = (const float*)d_in[15];
    const float* b1     = (const float*)d_in[16];
    const float* W2     = (const float*)d_in[17];
    const float* b2     = (const float*)d_in[18];
    const float* ln1_g  = (const float*)d_in[19];
    const float* ln1_b  = (const float*)d_in[20];
    const float* ln2_g  = (const float*)d_in[21];
    const float* ln2_b  = (const float*)d_in[22];
    const float* lnf_g  = (const float*)d_in[23];
    const float* lnf_b  = (const float*)d_in[24];
    const float* proj_W = (const float*)d_in[25];
    const float* proj_b = (const float*)d_in[26];

    cudaFuncSetAttribute(gemm_tc, cudaFuncAttributeMaxDynamicSharedMemorySize, SMEM_DYN);

    float* ws = nullptr;
    cudaGetSymbolAddress((void**)&ws, g_ws);
    __half* hw = nullptr;
    cudaGetSymbolAddress((void**)&hw, g_hws);

    float* h    = ws + O_H;
    float* mean = ws + O_MEAN;
    float* stdv = ws + O_STD;
    float* dot  = ws + O_DOT;
    float* ao   = ws + O_AO;
    float* att  = ws + O_ATT;
    float* x1   = ws + O_X1;
    float* y2   = ws + O_Y2;
    float* dec  = ws + O_DEC;
    float* qn2  = dot;  // reuse? no — keep separate small buffers inside dec tail is risky; use dedicated:
    // qn2/kn2 need CB*4*CD floats each = 32768; carve from unused front of 'dec'? dec is CBN*CP=493k — not free.
    // Put them after dec by extending is not possible; instead reuse att's tail? att used per layer... safest: static.
    static_assert(true, "");

    __half* xt_h  = hw + H_XT;
    __half* coefh = hw + H_COEF;
    __half* qh    = hw + H_Q;
    __half* kh    = hw + H_K;
    __half* vh    = hw + H_V;
    __half* qah   = hw + H_QA;
    __half* kah   = hw + H_KA;
    __half* prob  = hw + H_PROB;
    __half* rech  = hw + H_REC;
    __half* x1h   = hw + H_X1;
    __half* ffh   = hw + H_FF;
    __half* embWh = hw + H_EMBW;
    __half* Wqh   = hw + H_WQ;
    __half* Wkh   = hw + H_WK;
    __half* Wvh   = hw + H_WV;
    __half* Woh   = hw + H_WO;
    __half* W1h   = hw + H_W1;
    __half* W2h   = hw + H_W2;
    __half* pWh   = hw + H_PW;

    // qn2/kn2: small dedicated fp32 buffers at the end of ao during phases where ao unused?
    // ao is written by AV after qn2/kn2 consumed by softmax -> but softmax runs before AV, and
    // qn2 is read by softmax while dot was already computed. AV writes ao after softmax. Safe to
    // place qn2/kn2 in ao's first 64K floats? AV writes ao AFTER score_softmax consumed qn2/kn2. OK.
    float* qn2b = ao;                    // CB*4*CD floats
    float* kn2b = ao + (size_t)CB * 4 * CD;

    // ---- weight conversions (once per launch) ----
    f2h(emb_W, embWh, (long long)CD * CS);
    f2h(Wq, Wqh, (long long)2 * CD * CD);
    f2h(Wk, Wkh, (long long)2 * CD * CD);
    f2h(Wv, Wvh, (long long)2 * CD * CD);
    f2h(Wo, Woh, (long long)2 * CD * CD);
    f2h(W1, W1h, (long long)2 * CDF * CD);
    f2h(W2, W2h, (long long)2 * CDF * CD);
    f2h(proj_W, pWh, (long long)CP * CD);

    stats_kernel<<<CBN, 128>>>(x_enc, mean, stdv);
    norm_t_kernel<<<(int)((BND + 255) / 256), 256>>>(x_enc, mean, stdv, xt_h);

    // embedding: h fp32
    launch_tc(xt_h, embWh, h, emb_b, CBN, CD, CS, CS, CS, CD, 1,
              1, 1, 0, 0, 0, 0, 0, 0, 0);

    const long long ZAP = (long long)CD * KPAD;
    const long long ZD  = (long long)CD * CD;
    const long long BSTR = (long long)CN * 4 * CD;

    for (int l = 0; l < 2; l++) {
        swt_dec_kernel<<<CBN, 256>>>(h, h0 + (long long)l * CN * 3, h1 + (long long)l * CN * 3, coefh);

        // QKV -> fp16 outputs
        launch_tc(coefh, Wqh + (long long)l * CD * CD, (float*)qh, bq + (long long)l * CD,
                  CBN * 4, CD, CD, CD, CD, CD, 1, 1, 1, 0, 0, 0, 0, 0, 0, 2);
        launch_tc(coefh, Wkh + (long long)l * CD * CD, (float*)kh, bk + (long long)l * CD,
                  CBN * 4, CD, CD, CD, CD, CD, 1, 1, 1, 0, 0, 0, 0, 0, 0, 2);
        launch_tc(coefh, Wvh + (long long)l * CD * CD, (float*)vh, bv + (long long)l * CD,
                  CBN * 4, CD, CD, CD, CD, CD, 1, 1, 1, 0, 0, 0, 0, 0, 0, 2);

        {
            dim3 g2(16, KPAD / 32, CB * 4), b2d(32, 8);
            trans_kernel<<<g2, b2d>>>(qh, qah);
            trans_kernel<<<g2, b2d>>>(kh, kah);
        }
        rowsq_kernel<<<CB * 4 * CD, 128>>>(qah, qn2b);
        rowsq_kernel<<<CB * 4 * CD, 128>>>(kah, kn2b);

        // QK^T batched over z = b*4+m
        launch_tc(qah, kah, dot, nullptr, CD, CD, KPAD, KPAD, KPAD, CD, 1,
                  CB * 4, 1, ZAP, 0, ZAP, 0, ZD, 0, 0);

        score_softmax_kernel<<<CB * 4 * CD, 256>>>(dot, qn2b, kn2b, prob);

        // AV with scatter into coeffs layout [b][n][m][l] (fp32 out for swt_rec)
        launch_tc(prob, vh, ao, nullptr, CD, CN, CD, CD, 4 * CD, 1, 4 * CD,
                  CB * 4, 4,
                  4 * ZD, ZD,
                  BSTR, CD,
                  BSTR, CD,
                  0);

        swt_rec_kernel<<<CBN, 256>>>(ao, g0 + (long long)l * CN * 3, g1 + (long long)l * CN * 3, rech);

        launch_tc(rech, Woh + (long long)l * CD * CD, att, bo + (long long)l * CD,
                  CBN, CD, CD, CD, CD, CD, 1, 1, 1, 0, 0, 0, 0, 0, 0, 0);

        add_ln_kernel<<<CBN, 256>>>(h, att, ln1_g + (long long)l * CD, ln1_b + (long long)l * CD, x1, x1h);

        launch_tc(x1h, W1h + (long long)l * CDF * CD, (float*)ffh, b1 + (long long)l * CDF,
                  CBN, CDF, CD, CD, CD, CDF, 1, 1, 1, 0, 0, 0, 0, 0, 0, 3);
        launch_tc(ffh, W2h + (long long)l * CD * CDF, y2, b2 + (long long)l * CD,
                  CBN, CD, CDF, CDF, CDF, CD, 1, 1, 1, 0, 0, 0, 0, 0, 0, 0);

        add_ln_kernel<<<CBN, 256>>>(x1, y2, ln2_g + (long long)l * CD, ln2_b + (long long)l * CD, h, nullptr);
    }

    add_ln_kernel<<<CBN, 256>>>(h, nullptr, lnf_g, lnf_b, nullptr, x1h);
    launch_tc(x1h, pWh, dec, proj_b, CBN, CP, CD, CD, CD, CP, 1,
              1, 1, 0, 0, 0, 0, 0, 0, 0);

    out_kernel<<<(CB * CP * CN + 255) / 256, 256>>>(dec, mean, stdv, (float*)d_out);
    if (out_size >= CB * CP * CN + 2 * CBN) {
        aux_out_kernel<<<(CBN + 255) / 256, 256>>>(mean, stdv, (float*)d_out);
    }
}

// round 11
// speedup vs baseline: 6.7046x; 1.1098x over previous
#include <cuda_runtime.h>
#include <cuda_fp16.h>
#include <math.h>
#include <stdint.h>

#define CB 16
#define CS 512
#define CN 321
#define CD 512
#define CDF 2048
#define CP 96
#define KPAD 384
#define CBN (CB*CN)
#define BND ((size_t)CBN*CD)
#define BNMD ((size_t)CBN*4*CD)
#define QAPAD ((size_t)CB*4*CD*KPAD)
#define ATT ((size_t)CB*4*CD*CD)
#define ALPHA_ 0.3f

// ---------------- fp32 workspace ----------------
#define O_H    ((size_t)0)
#define O_MEAN (O_H + BND)
#define O_STD  (O_MEAN + CBN)
#define O_DOT  (O_STD + CBN)
#define O_AO   (O_DOT + ATT)
#define O_ATT  (O_AO + BNMD)
#define O_X1   (O_ATT + BND)
#define O_Y2   (O_X1 + BND)
#define O_DEC  (O_Y2 + BND)
#define WS_TOTAL (O_DEC + (size_t)CBN*CP)
__device__ float g_ws[WS_TOTAL];

// ---------------- fp16 workspace ----------------
#define H_XT   ((size_t)0)
#define H_COEF (H_XT + BND)
#define H_Q    (H_COEF + BNMD)
#define H_K    (H_Q + BNMD)
#define H_V    (H_K + BNMD)
#define H_QA   (H_V + BNMD)
#define H_KA   (H_QA + QAPAD)
#define H_PROB (H_KA + QAPAD)
#define H_REC  (H_PROB + ATT)
#define H_X1   (H_REC + BND)
#define H_FF   (H_X1 + BND)
#define H_EMBW (H_FF + (size_t)CBN*CDF)
#define H_WQ   (H_EMBW + (size_t)CD*CS)
#define H_WK   (H_WQ + (size_t)2*CD*CD)
#define H_WV   (H_WK + (size_t)2*CD*CD)
#define H_WO   (H_WV + (size_t)2*CD*CD)
#define H_W1   (H_WO + (size_t)2*CD*CD)
#define H_W2   (H_W1 + (size_t)2*CDF*CD)
#define H_PW   (H_W2 + (size_t)2*CDF*CD)
#define HW_TOTAL (H_PW + (size_t)CP*CD)
__device__ __align__(16) __half g_hws[HW_TOTAL];

// ---------------- helpers ----------------
__device__ __forceinline__ uint32_t smem_u32(const void* p) {
    uint32_t a;
    asm("{ .reg .u64 t; cvta.to.shared.u64 t, %1; cvt.u32.u64 %0, t; }" : "=r"(a) : "l"(p));
    return a;
}
__device__ __forceinline__ void cp16(uint32_t dst, const void* src, int sz) {
    asm volatile("cp.async.cg.shared.global [%0], [%1], 16, %2;"
                 :: "r"(dst), "l"(src), "r"(sz));
}
__device__ __forceinline__ void cp_commit() { asm volatile("cp.async.commit_group;" ::: "memory"); }
__device__ __forceinline__ void cp_wait1()  { asm volatile("cp.async.wait_group 1;" ::: "memory"); }
__device__ __forceinline__ void cp_wait0()  { asm volatile("cp.async.wait_group 0;" ::: "memory"); }

#define ASTRIDE 72                    /* halves; 144B pitch -> LDSM conflict-free */
#define ABUF (128*ASTRIDE)            /* halves per buffer */
#define ABUF_B (ABUF*2)
#define SMEM_DYN (4*ABUF_B)           /* 73728 bytes */

// async load 128 rows x 64 halves of a K-chunk, zero-pad OOB rows
__device__ __forceinline__ void load_chunk(const __half* __restrict__ g, int rows, int ld,
                                           int k0, uint32_t smbase, int tid) {
    #pragma unroll
    for (int i = 0; i < 4; i++) {
        int idx = tid + (i << 8);
        int r = idx >> 3, c = idx & 7;
        int ok = r < rows;
        const __half* src = g + (long long)(ok ? r : 0) * ld + k0 + c * 8;
        cp16(smbase + (uint32_t)(r * ASTRIDE + c * 8) * 2u, src, ok ? 16 : 0);
    }
}

// ============ generic batched NT GEMM via mma.sync fp16 + ldmatrix ============
// C[row,col] = sum_k A[row,k]*B[col,k] (+bias[col])
// act bit0 = gelu, bit1 = fp16 output (C as __half*)
__global__ __launch_bounds__(256, 2) void gemm_tc(
    const __half* __restrict__ A, const __half* __restrict__ Bm,
    float* __restrict__ C, const float* __restrict__ bias,
    int M, int Nn, int Kd, int lda, int ldb,
    long long ldcr, long long ldcc, int bdiv,
    long long sAh, long long sAl, long long sBh, long long sBl,
    long long sCh, long long sCl, int act)
{
    extern __shared__ __half smh[];
    const int tid = threadIdx.x;
    const int wid = tid >> 5, lane = tid & 31;
    const int gid = lane >> 2, tig = lane & 3;
    const int wr = wid & 3, wc = wid >> 2;

    int z = blockIdx.z;
    int zh = z / bdiv, zl = z % bdiv;
    A  += zh * sAh + zl * sAl;
    Bm += zh * sBh + zl * sBl;
    long long coff = zh * sCh + zl * sCl;

    int m0 = blockIdx.x * 128, n0 = blockIdx.y * 128;
    int mrem = M - m0, nrem = Nn - n0;
    const __half* Ag = A + (long long)m0 * lda;
    const __half* Bg = Bm + (long long)n0 * ldb;

    uint32_t smb = smem_u32(smh);
    const uint32_t aoff[2] = { smb, smb + ABUF_B };
    const uint32_t boff[2] = { smb + 2 * ABUF_B, smb + 3 * ABUF_B };

    // ldmatrix per-lane row offsets (halves)
    const int aRow = (wr * 32 + (lane & 15)) * ASTRIDE + (lane >> 4) * 8;
    const int mID = lane >> 3, rID = lane & 7;
    const int bRow = (wc * 64 + ((mID >> 1) << 3) + rID) * ASTRIDE + (mID & 1) * 8;

    float c[2][8][4];
    #pragma unroll
    for (int i = 0; i < 2; i++)
        #pragma unroll
        for (int j = 0; j < 8; j++)
            #pragma unroll
            for (int r = 0; r < 4; r++) c[i][j][r] = 0.f;

    const int NC = Kd >> 6;   // K chunks of 64
    load_chunk(Ag, mrem, lda, 0, aoff[0], tid);
    load_chunk(Bg, nrem, ldb, 0, boff[0], tid);
    cp_commit();

    for (int ch = 0; ch < NC; ch++) {
        int cur = ch & 1;
        if (ch + 1 < NC) {
            int nxt = cur ^ 1;
            load_chunk(Ag, mrem, lda, (ch + 1) << 6, aoff[nxt], tid);
            load_chunk(Bg, nrem, ldb, (ch + 1) << 6, boff[nxt], tid);
            cp_commit();
            cp_wait1();
        } else {
            cp_wait0();
        }
        __syncthreads();

        uint32_t aB = aoff[cur], bB = boff[cur];
        #pragma unroll
        for (int ks = 0; ks < 4; ks++) {
            int kc = ks << 4;
            uint32_t a[2][4], b[8][2];
            #pragma unroll
            for (int i = 0; i < 2; i++) {
                uint32_t ad = aB + (uint32_t)(aRow + i * 16 * ASTRIDE + kc) * 2u;
                asm volatile("ldmatrix.sync.aligned.m8n8.x4.shared.b16 {%0,%1,%2,%3}, [%4];"
                    : "=r"(a[i][0]), "=r"(a[i][1]), "=r"(a[i][2]), "=r"(a[i][3]) : "r"(ad));
            }
            #pragma unroll
            for (int jp = 0; jp < 4; jp++) {
                uint32_t bd = bB + (uint32_t)(bRow + jp * 16 * ASTRIDE + kc) * 2u;
                asm volatile("ldmatrix.sync.aligned.m8n8.x4.shared.b16 {%0,%1,%2,%3}, [%4];"
                    : "=r"(b[2*jp][0]), "=r"(b[2*jp][1]),
                      "=r"(b[2*jp+1][0]), "=r"(b[2*jp+1][1]) : "r"(bd));
            }
            #pragma unroll
            for (int i = 0; i < 2; i++)
                #pragma unroll
                for (int j = 0; j < 8; j++) {
                    asm volatile(
                        "mma.sync.aligned.m16n8k16.row.col.f32.f16.f16.f32 "
                        "{%0,%1,%2,%3}, {%4,%5,%6,%7}, {%8,%9}, {%0,%1,%2,%3};"
                        : "+f"(c[i][j][0]), "+f"(c[i][j][1]),
                          "+f"(c[i][j][2]), "+f"(c[i][j][3])
                        : "r"(a[i][0]), "r"(a[i][1]), "r"(a[i][2]), "r"(a[i][3]),
                          "r"(b[j][0]), "r"(b[j][1]));
                }
        }
        __syncthreads();
    }

    // epilogue
    #pragma unroll
    for (int i = 0; i < 2; i++) {
        int rbase = wr * 32 + i * 16 + gid;
        #pragma unroll
        for (int half = 0; half < 2; half++) {
            int rloc = rbase + half * 8;
            if (rloc >= mrem) continue;
            long long row = m0 + rloc;
            #pragma unroll
            for (int j = 0; j < 8; j++) {
                #pragma unroll
                for (int q = 0; q < 2; q++) {
                    int cloc = wc * 64 + j * 8 + tig * 2 + q;
                    if (cloc >= nrem) continue;
                    int col = n0 + cloc;
                    float v = c[i][j][half * 2 + q];
                    if (bias) v += bias[col];
                    if (act & 1) v = 0.5f * v * (1.f + erff(v * 0.70710678118654752f));
                    long long off = coff + row * ldcr + (long long)col * ldcc;
                    if (act & 2) ((__half*)C)[off] = __float2half(v);
                    else C[off] = v;
                }
            }
        }
    }
}

// ---------------- all weights f32 -> f16 in one launch ----------------
#define SEG0 ((long long)CD*CS)          /* 262144  embW  */
#define SEG1 (SEG0 + (long long)2*CD*CD) /* +Wq */
#define SEG2 (SEG1 + (long long)2*CD*CD)
#define SEG3 (SEG2 + (long long)2*CD*CD)
#define SEG4 (SEG3 + (long long)2*CD*CD)
#define SEG5 (SEG4 + (long long)2*CDF*CD)
#define SEG6 (SEG5 + (long long)2*CDF*CD)
#define SEG7 (SEG6 + (long long)CP*CD)   /* total 6602752 */
__global__ void f2h_all(const float* __restrict__ s0, const float* __restrict__ s1,
                        const float* __restrict__ s2, const float* __restrict__ s3,
                        const float* __restrict__ s4, const float* __restrict__ s5,
                        const float* __restrict__ s6, const float* __restrict__ s7,
                        __half* __restrict__ out)
{
    long long i = (long long)blockIdx.x * blockDim.x + threadIdx.x;
    if (i >= SEG7) return;
    float v;
    if      (i < SEG0) v = s0[i];
    else if (i < SEG1) v = s1[i - SEG0];
    else if (i < SEG2) v = s2[i - SEG1];
    else if (i < SEG3) v = s3[i - SEG2];
    else if (i < SEG4) v = s4[i - SEG3];
    else if (i < SEG5) v = s5[i - SEG4];
    else if (i < SEG6) v = s6[i - SEG5];
    else               v = s7[i - SEG6];
    out[i] = __float2half(v);
}

// ---------------- per-(b,n) stats over S ----------------
__global__ void stats_kernel(const float* __restrict__ x, float* __restrict__ mean,
                             float* __restrict__ stdv)
{
    int bn = blockIdx.x;
    int b = bn / CN, n = bn % CN;
    const float* p = x + (long long)b * CS * CN + n;
    float s = 0.f, s2 = 0.f;
    for (int i = threadIdx.x; i < CS; i += blockDim.x) {
        float v = p[(long long)i * CN];
        s += v; s2 += v * v;
    }
    __shared__ float rs[128], rq[128];
    rs[threadIdx.x] = s; rq[threadIdx.x] = s2; __syncthreads();
    for (int o = 64; o > 0; o >>= 1) {
        if (threadIdx.x < o) { rs[threadIdx.x] += rs[threadIdx.x + o]; rq[threadIdx.x] += rq[threadIdx.x + o]; }
        __syncthreads();
    }
    if (threadIdx.x == 0) {
        float mu = rs[0] / CS;
        float var = rq[0] / CS - mu * mu;
        mean[bn] = mu;
        stdv[bn] = sqrtf(var + 1e-5f);
    }
}

__global__ void norm_t_kernel(const float* __restrict__ x, const float* __restrict__ mean,
                              const float* __restrict__ stdv, __half* __restrict__ xt)
{
    long long idx = (long long)blockIdx.x * blockDim.x + threadIdx.x;
    if (idx >= (long long)BND) return;
    int s = (int)(idx & (CS - 1));
    long long bn = idx >> 9;
    int b = (int)(bn / CN), n = (int)(bn % CN);
    xt[idx] = __float2half((x[((long long)b * CS + s) * CN + n] - mean[bn]) / stdv[bn]);
}

// ---------------- SWT decomposition (fp32 in, fp16 out) ----------------
__global__ void swt_dec_kernel(const float* __restrict__ h,
                               const float* __restrict__ f0g, const float* __restrict__ f1g,
                               __half* __restrict__ coef)
{
    int bn = blockIdx.x; int n = bn % CN;
    __shared__ float a[CD], b[CD];
    const float* hp = h + (long long)bn * CD;
    for (int d = threadIdx.x; d < CD; d += blockDim.x) a[d] = hp[d];
    float l0[3], l1[3];
    #pragma unroll
    for (int t = 0; t < 3; t++) { l0[t] = f0g[n * 3 + t]; l1[t] = f1g[n * 3 + t]; }
    __syncthreads();
    __half* cf = coef + (long long)bn * 4 * CD;
    for (int d = threadIdx.x; d < CD; d += blockDim.x) {
        int im = (d - 1) & 511, ip = (d + 1) & 511;
        cf[3 * CD + d] = __float2half(l1[0] * a[im] + l1[1] * a[d] + l1[2] * a[ip]);
        b[d]           = l0[0] * a[im] + l0[1] * a[d] + l0[2] * a[ip];
    }
    __syncthreads();
    for (int d = threadIdx.x; d < CD; d += blockDim.x) {
        int i0 = (d - 1) & 511, i1 = (d + 1) & 511, i2 = (d + 3) & 511;
        cf[2 * CD + d] = __float2half(l1[0] * b[i0] + l1[1] * b[i1] + l1[2] * b[i2]);
        a[d]           = l0[0] * b[i0] + l0[1] * b[i1] + l0[2] * b[i2];
    }
    __syncthreads();
    for (int d = threadIdx.x; d < CD; d += blockDim.x) {
        int i0 = (d - 2) & 511, i1 = (d + 2) & 511, i2 = (d + 6) & 511;
        cf[1 * CD + d] = __float2half(l1[0] * a[i0] + l1[1] * a[i1] + l1[2] * a[i2]);
        cf[0 * CD + d] = __float2half(l0[0] * a[i0] + l0[1] * a[i1] + l0[2] * a[i2]);
    }
}

// ---------------- SWT reconstruction (fp32 in, fp16 out) ----------------
__global__ void swt_rec_kernel(const float* __restrict__ c,
                               const float* __restrict__ g0g, const float* __restrict__ g1g,
                               __half* __restrict__ out)
{
    int bn = blockIdx.x; int n = bn % CN;
    const float* cp = c + (long long)bn * 4 * CD;
    __shared__ float a[CD], b[CD], det[CD];
    float f0[3], f1[3];
    #pragma unroll
    for (int t = 0; t < 3; t++) { f0[t] = g0g[n * 3 + t]; f1[t] = g1g[n * 3 + t]; }
    for (int d = threadIdx.x; d < CD; d += blockDim.x) { a[d] = cp[d]; det[d] = cp[CD + d]; }
    __syncthreads();
    for (int d = threadIdx.x; d < CD; d += blockDim.x) {
        int i0 = (d - 6) & 511, i1 = (d - 2) & 511, i2 = (d + 2) & 511;
        b[d] = 0.5f * (f0[0] * a[i0] + f0[1] * a[i1] + f0[2] * a[i2]
                     + f1[0] * det[i0] + f1[1] * det[i1] + f1[2] * det[i2]);
    }
    __syncthreads();
    for (int d = threadIdx.x; d < CD; d += blockDim.x) det[d] = cp[2 * CD + d];
    __syncthreads();
    for (int d = threadIdx.x; d < CD; d += blockDim.x) {
        int i0 = (d - 3) & 511, i1 = (d - 1) & 511, i2 = (d + 1) & 511;
        a[d] = 0.5f * (f0[0] * b[i0] + f0[1] * b[i1] + f0[2] * b[i2]
                     + f1[0] * det[i0] + f1[1] * det[i1] + f1[2] * det[i2]);
    }
    __syncthreads();
    for (int d = threadIdx.x; d < CD; d += blockDim.x) det[d] = cp[3 * CD + d];
    __syncthreads();
    __half* op = out + (long long)bn * CD;
    for (int d = threadIdx.x; d < CD; d += blockDim.x) {
        int i0 = (d - 1) & 511, i2 = (d + 1) & 511;
        op[d] = __float2half(0.5f * (f0[0] * a[i0] + f0[1] * a[d] + f0[2] * a[i2]
                                   + f1[0] * det[i0] + f1[1] * det[d] + f1[2] * det[i2]));
    }
}

// ---------------- transpose fp16 [b][n][m][e] -> [b][m][e][KPAD] ----------------
__global__ void trans_kernel(const __half* __restrict__ in, __half* __restrict__ out)
{
    int z = blockIdx.z; int b = z >> 2, m = z & 3;
    __shared__ __half t[32][34];
    int e0 = blockIdx.x * 32, n0 = blockIdx.y * 32;
    int tx = threadIdx.x, ty = threadIdx.y;
    #pragma unroll
    for (int j = 0; j < 4; j++) {
        int e = e0 + tx, n = n0 + ty + j * 8;
        t[ty + j * 8][tx] = (n < CN) ? in[(((long long)b * CN + n) * 4 + m) * CD + e]
                                     : __float2half(0.f);
    }
    __syncthreads();
    #pragma unroll
    for (int j = 0; j < 4; j++) {
        int n = n0 + tx, e = e0 + ty + j * 8;
        out[(((long long)b * 4 + m) * CD + e) * KPAD + n] = t[tx][ty + j * 8];
    }
}

// ---------------- row squared-norm (fp16 rows, stride KPAD) ----------------
__global__ void rowsq_kernel(const __half* __restrict__ in, float* __restrict__ out)
{
    int r = blockIdx.x;
    const __half* p = in + (long long)r * KPAD;
    float s = 0.f;
    for (int i = threadIdx.x; i < CN; i += blockDim.x) { float v = __half2float(p[i]); s += v * v; }
    __shared__ float rs[128];
    rs[threadIdx.x] = s; __syncthreads();
    for (int o = 64; o > 0; o >>= 1) {
        if (threadIdx.x < o) rs[threadIdx.x] += rs[threadIdx.x + o];
        __syncthreads();
    }
    if (threadIdx.x == 0) out[r] = rs[0];
}

// ---------------- wedge score + softmax (fp32 in, fp16 probs out) ----------------
__global__ void score_softmax_kernel(const float* __restrict__ dot,
                                     const float* __restrict__ qn2,
                                     const float* __restrict__ kn2,
                                     __half* __restrict__ prob)
{
    int row = blockIdx.x;
    int z = row >> 9;
    float q2 = qn2[row];
    const float* p = dot + (long long)row * CD;
    __half* pr = prob + (long long)row * CD;
    const float* k2 = kn2 + (long long)z * CD;
    const float scale = 1.f / sqrtf((float)CN);
    int t = threadIdx.x;
    float sc[2];
    float mx = -1e30f;
    #pragma unroll
    for (int j = 0; j < 2; j++) {
        int s = t + j * 256;
        float d = p[s];
        float w = sqrtf(fmaxf(q2 * k2[s] - d * d, 0.f) + 1e-8f);
        float v = ((1.f - ALPHA_) * d + ALPHA_ * w) * scale;
        sc[j] = v;
        mx = fmaxf(mx, v);
    }
    __shared__ float red[256];
    red[t] = mx; __syncthreads();
    for (int o = 128; o > 0; o >>= 1) {
        if (t < o) red[t] = fmaxf(red[t], red[t + o]);
        __syncthreads();
    }
    mx = red[0]; __syncthreads();
    float sum = 0.f;
    #pragma unroll
    for (int j = 0; j < 2; j++) { sc[j] = expf(sc[j] - mx); sum += sc[j]; }
    red[t] = sum; __syncthreads();
    for (int o = 128; o > 0; o >>= 1) {
        if (t < o) red[t] += red[t + o];
        __syncthreads();
    }
    float inv = 1.f / red[0];
    #pragma unroll
    for (int j = 0; j < 2; j++) pr[t + j * 256] = __float2half(sc[j] * inv);
}

// ---------------- add + layernorm ----------------
__global__ void add_ln_kernel(const float* __restrict__ x, const float* __restrict__ y,
                              const float* __restrict__ g, const float* __restrict__ bb,
                              float* __restrict__ out, __half* __restrict__ outh)
{
    int bn = blockIdx.x;
    const float* xp = x + (long long)bn * CD;
    const float* yp = y ? y + (long long)bn * CD : nullptr;
    int t = threadIdx.x;
    float v[2];
    float s = 0.f;
    #pragma unroll
    for (int j = 0; j < 2; j++) {
        int d = t + j * 256;
        v[j] = xp[d] + (yp ? yp[d] : 0.f);
        s += v[j];
    }
    __shared__ float red[256];
    red[t] = s; __syncthreads();
    for (int o = 128; o > 0; o >>= 1) { if (t < o) red[t] += red[t + o]; __syncthreads(); }
    float mu = red[0] / CD; __syncthreads();
    float s2 = 0.f;
    #pragma unroll
    for (int j = 0; j < 2; j++) { float dv = v[j] - mu; s2 += dv * dv; }
    red[t] = s2; __syncthreads();
    for (int o = 128; o > 0; o >>= 1) { if (t < o) red[t] += red[t + o]; __syncthreads(); }
    float inv = 1.f / sqrtf(red[0] / CD + 1e-5f);
    #pragma unroll
    for (int j = 0; j < 2; j++) {
        int d = t + j * 256;
        float r = (v[j] - mu) * inv * g[d] + bb[d];
        if (out)  out[(long long)bn * CD + d] = r;
        if (outh) outh[(long long)bn * CD + d] = __float2half(r);
    }
}

// ---------------- final output de-normalization ----------------
__global__ void out_kernel(const float* __restrict__ dec, const float* __restrict__ mean,
                           const float* __restrict__ stdv, float* __restrict__ out)
{
    int idx = blockIdx.x * blockDim.x + threadIdx.x;
    if (idx >= CB * CP * CN) return;
    int n = idx % CN;
    int p = (idx / CN) % CP;
    int b = idx / (CN * CP);
    int bn = b * CN + n;
    out[idx] = dec[(long long)bn * CP + p] * stdv[bn] + mean[bn];
}

__global__ void aux_out_kernel(const float* __restrict__ mean, const float* __restrict__ stdv,
                               float* __restrict__ out)
{
    int i = blockIdx.x * blockDim.x + threadIdx.x;
    if (i >= CBN) return;
    out[CB * CP * CN + i] = mean[i];
    out[CB * CP * CN + CBN + i] = stdv[i];
}

// ---------------- host orchestration ----------------
static void launch_tc(const __half* A, const __half* B, float* C, const float* bias,
                      int M, int Nn, int Kd, int lda, int ldb,
                      long long ldcr, long long ldcc,
                      int batches, int bdiv,
                      long long sAh, long long sAl,
                      long long sBh, long long sBl,
                      long long sCh, long long sCl, int act)
{
    dim3 grid((M + 127) / 128, (Nn + 127) / 128, batches);
    gemm_tc<<<grid, 256, SMEM_DYN>>>(A, B, C, bias, M, Nn, Kd, lda, ldb, ldcr, ldcc,
                                     bdiv, sAh, sAl, sBh, sBl, sCh, sCl, act);
}

extern "C" void kernel_launch(void* const* d_in, const int* in_sizes, int n_in,
                              void* d_out, int out_size)
{
    (void)in_sizes; (void)n_in;
    const float* x_enc  = (const float*)d_in[0];
    const float* emb_W  = (const float*)d_in[1];
    const float* emb_b  = (const float*)d_in[2];
    const float* h0     = (const float*)d_in[3];
    const float* h1     = (const float*)d_in[4];
    const float* g0     = (const float*)d_in[5];
    const float* g1     = (const float*)d_in[6];
    const float* Wq     = (const float*)d_in[7];
    const float* bq     = (const float*)d_in[8];
    const float* Wk     = (const float*)d_in[9];
    const float* bk     = (const float*)d_in[10];
    const float* Wv     = (const float*)d_in[11];
    const float* bv     = (const float*)d_in[12];
    const float* Wo     = (const float*)d_in[13];
    const float* bo     = (const float*)d_in[14];
    const float* W1     = (const float*)d_in[15];
    const float* b1     = (const float*)d_in[16];
    const float* W2     = (const float*)d_in[17];
    const float* b2     = (const float*)d_in[18];
    const float* ln1_g  = (const float*)d_in[19];
    const float* ln1_b  = (const float*)d_in[20];
    const float* ln2_g  = (const float*)d_in[21];
    const float* ln2_b  = (const float*)d_in[22];
    const float* lnf_g  = (const float*)d_in[23];
    const float* lnf_b  = (const float*)d_in[24];
    const float* proj_W = (const float*)d_in[25];
    const float* proj_b = (const float*)d_in[26];

    cudaFuncSetAttribute(gemm_tc, cudaFuncAttributeMaxDynamicSharedMemorySize, SMEM_DYN);

    float* ws = nullptr;
    cudaGetSymbolAddress((void**)&ws, g_ws);
    __half* hw = nullptr;
    cudaGetSymbolAddress((void**)&hw, g_hws);

    float* h    = ws + O_H;
    float* mean = ws + O_MEAN;
    float* stdv = ws + O_STD;
    float* dot  = ws + O_DOT;
    float* ao   = ws + O_AO;
    float* att  = ws + O_ATT;
    float* x1   = ws + O_X1;
    float* y2   = ws + O_Y2;
    float* dec  = ws + O_DEC;

    __half* xt_h  = hw + H_XT;
    __half* coefh = hw + H_COEF;
    __half* qh    = hw + H_Q;
    __half* kh    = hw + H_K;
    __half* vh    = hw + H_V;
    __half* qah   = hw + H_QA;
    __half* kah   = hw + H_KA;
    __half* prob  = hw + H_PROB;
    __half* rech  = hw + H_REC;
    __half* x1h   = hw + H_X1;
    __half* ffh   = hw + H_FF;
    __half* embWh = hw + H_EMBW;
    __half* Wqh   = hw + H_WQ;
    __half* Wkh   = hw + H_WK;
    __half* Wvh   = hw + H_WV;
    __half* Woh   = hw + H_WO;
    __half* W1h   = hw + H_W1;
    __half* W2h   = hw + H_W2;
    __half* pWh   = hw + H_PW;

    // qn2/kn2 borrow the front of ao: softmax consumes them before AV writes ao
    float* qn2b = ao;
    float* kn2b = ao + (size_t)CB * 4 * CD;

    // all weight conversions in one launch
    f2h_all<<<(int)((SEG7 + 255) / 256), 256>>>(emb_W, Wq, Wk, Wv, Wo, W1, W2, proj_W, embWh);

    stats_kernel<<<CBN, 128>>>(x_enc, mean, stdv);
    norm_t_kernel<<<(int)((BND + 255) / 256), 256>>>(x_enc, mean, stdv, xt_h);

    launch_tc(xt_h, embWh, h, emb_b, CBN, CD, CS, CS, CS, CD, 1,
              1, 1, 0, 0, 0, 0, 0, 0, 0);

    const long long ZAP = (long long)CD * KPAD;
    const long long ZD  = (long long)CD * CD;
    const long long BSTR = (long long)CN * 4 * CD;

    for (int l = 0; l < 2; l++) {
        swt_dec_kernel<<<CBN, 256>>>(h, h0 + (long long)l * CN * 3, h1 + (long long)l * CN * 3, coefh);

        launch_tc(coefh, Wqh + (long long)l * CD * CD, (float*)qh, bq + (long long)l * CD,
                  CBN * 4, CD, CD, CD, CD, CD, 1, 1, 1, 0, 0, 0, 0, 0, 0, 2);
        launch_tc(coefh, Wkh + (long long)l * CD * CD, (float*)kh, bk + (long long)l * CD,
                  CBN * 4, CD, CD, CD, CD, CD, 1, 1, 1, 0, 0, 0, 0, 0, 0, 2);
        launch_tc(coefh, Wvh + (long long)l * CD * CD, (float*)vh, bv + (long long)l * CD,
                  CBN * 4, CD, CD, CD, CD, CD, 1, 1, 1, 0, 0, 0, 0, 0, 0, 2);

        {
            dim3 g2(16, KPAD / 32, CB * 4), b2d(32, 8);
            trans_kernel<<<g2, b2d>>>(qh, qah);
            trans_kernel<<<g2, b2d>>>(kh, kah);
        }
        rowsq_kernel<<<CB * 4 * CD, 128>>>(qah, qn2b);
        rowsq_kernel<<<CB * 4 * CD, 128>>>(kah, kn2b);

        launch_tc(qah, kah, dot, nullptr, CD, CD, KPAD, KPAD, KPAD, CD, 1,
                  CB * 4, 1, ZAP, 0, ZAP, 0, ZD, 0, 0);

        score_softmax_kernel<<<CB * 4 * CD, 256>>>(dot, qn2b, kn2b, prob);

        launch_tc(prob, vh, ao, nullptr, CD, CN, CD, CD, 4 * CD, 1, 4 * CD,
                  CB * 4, 4,
                  4 * ZD, ZD,
                  BSTR, CD,
                  BSTR, CD,
                  0);

        swt_rec_kernel<<<CBN, 256>>>(ao, g0 + (long long)l * CN * 3, g1 + (long long)l * CN * 3, rech);

        launch_tc(rech, Woh + (long long)l * CD * CD, att, bo + (long long)l * CD,
                  CBN, CD, CD, CD, CD, CD, 1, 1, 1, 0, 0, 0, 0, 0, 0, 0);

        add_ln_kernel<<<CBN, 256>>>(h, att, ln1_g + (long long)l * CD, ln1_b + (long long)l * CD, x1, x1h);

        launch_tc(x1h, W1h + (long long)l * CDF * CD, (float*)ffh, b1 + (long long)l * CDF,
                  CBN, CDF, CD, CD, CD, CDF, 1, 1, 1, 0, 0, 0, 0, 0, 0, 3);
        launch_tc(ffh, W2h + (long long)l * CD * CDF, y2, b2 + (long long)l * CD,
                  CBN, CD, CDF, CDF, CDF, CD, 1, 1, 1, 0, 0, 0, 0, 0, 0, 0);

        add_ln_kernel<<<CBN, 256>>>(x1, y2, ln2_g + (long long)l * CD, ln2_b + (long long)l * CD, h, nullptr);
    }

    add_ln_kernel<<<CBN, 256>>>(h, nullptr, lnf_g, lnf_b, nullptr, x1h);
    launch_tc(x1h, pWh, dec, proj_b, CBN, CP, CD, CD, CD, CP, 1,
              1, 1, 0, 0, 0, 0, 0, 0, 0);

    out_kernel<<<(CB * CP * CN + 255) / 256, 256>>>(dec, mean, stdv, (float*)d_out);
    if (out_size >= CB * CP * CN + 2 * CBN) {
        aux_out_kernel<<<(CBN + 255) / 256, 256>>>(mean, stdv, (float*)d_out);
    }
}

// round 13
// speedup vs baseline: 7.0542x; 1.0521x over previous
#include <cuda_runtime.h>
#include <cuda_fp16.h>
#include <math.h>
#include <stdint.h>

#define CB 16
#define CS 512
#define CN 321
#define CD 512
#define CDF 2048
#define CP 96
#define KPAD 384
#define CBN (CB*CN)
#define BND ((size_t)CBN*CD)
#define BNMD ((size_t)CBN*4*CD)
#define QAPAD ((size_t)CB*4*CD*KPAD)
#define ATT ((size_t)CB*4*CD*CD)
#define ALPHA_ 0.3f

// ---------------- fp32 workspace ----------------
#define O_H    ((size_t)0)
#define O_MEAN (O_H + BND)
#define O_STD  (O_MEAN + CBN)
#define O_DOT  (O_STD + CBN)
#define O_AO   (O_DOT + ATT)
#define O_ATT  (O_AO + BNMD)
#define O_X1   (O_ATT + BND)
#define O_Y2   (O_X1 + BND)
#define O_DEC  (O_Y2 + BND)
#define WS_TOTAL (O_DEC + (size_t)CBN*CP)
__device__ float g_ws[WS_TOTAL];

// ---------------- fp16 workspace ----------------
#define H_XT   ((size_t)0)
#define H_COEF (H_XT + BND)
#define H_Q    (H_COEF + BNMD)
#define H_K    (H_Q + BNMD)
#define H_V    (H_K + BNMD)
#define H_QA   (H_V + BNMD)
#define H_KA   (H_QA + QAPAD)
#define H_PROB (H_KA + QAPAD)
#define H_REC  (H_PROB + ATT)
#define H_X1   (H_REC + BND)
#define H_FF   (H_X1 + BND)
#define H_EMBW (H_FF + (size_t)CBN*CDF)
#define H_WQ   (H_EMBW + (size_t)CD*CS)
#define H_WK   (H_WQ + (size_t)2*CD*CD)
#define H_WV   (H_WK + (size_t)2*CD*CD)
#define H_WO   (H_WV + (size_t)2*CD*CD)
#define H_W1   (H_WO + (size_t)2*CD*CD)
#define H_W2   (H_W1 + (size_t)2*CDF*CD)
#define H_PW   (H_W2 + (size_t)2*CDF*CD)
#define HW_TOTAL (H_PW + (size_t)CP*CD)
__device__ __align__(16) __half g_hws[HW_TOTAL];

// ---------------- helpers ----------------
__device__ __forceinline__ uint32_t smem_u32(const void* p) {
    uint32_t a;
    asm("{ .reg .u64 t; cvta.to.shared.u64 t, %1; cvt.u32.u64 %0, t; }" : "=r"(a) : "l"(p));
    return a;
}
__device__ __forceinline__ void cp16(uint32_t dst, const void* src, int sz) {
    asm volatile("cp.async.cg.shared.global [%0], [%1], 16, %2;"
                 :: "r"(dst), "l"(src), "r"(sz));
}
__device__ __forceinline__ void cp_commit() { asm volatile("cp.async.commit_group;" ::: "memory"); }

#define ASTRIDE 72                    /* halves; 144B pitch -> LDSM conflict-free */

// async load ROWS x 64 halves of a K-chunk, zero-pad rows >= rows
template<int ROWS, int NT>
__device__ __forceinline__ void load_chunk(const __half* __restrict__ g, int rows, int ld,
                                           int k0, uint32_t smbase, int tid) {
    #pragma unroll
    for (int i = 0; i < ROWS * 8 / NT; i++) {
        int idx = tid + i * NT;
        int r = idx >> 3, c = idx & 7;
        int ok = r < rows;
        const __half* src = g + (long long)(ok ? r : 0) * ld + k0 + c * 8;
        cp16(smbase + (uint32_t)(r * ASTRIDE + c * 8) * 2u, src, ok ? 16 : 0);
    }
}

#define SMEM_128 (3*(128+128)*ASTRIDE*2)   /* 110592 */
#define SMEM_64  (2*( 64+128)*ASTRIDE*2)   /* 55296  */

// ============ generic batched NT GEMM via mma.sync fp16 + ldmatrix ============
// C[row,col] = sum_k A[row,k]*B[col,k] (+bias[col])
// act bit0 = gelu, bit1 = fp16 output (C as __half*)
// BM in {64,128}; BN=128; NT = BM*2 threads; warp tile 32x64.
template<int BM, int NT, int NSTAGE>
__global__ __launch_bounds__(NT, (BM == 128) ? 2 : 4) void gemm_tc(
    const __half* __restrict__ A, const __half* __restrict__ Bm,
    float* __restrict__ C, const float* __restrict__ bias,
    int M, int Nn, int Kd, int lda, int ldb,
    long long ldcr, long long ldcc, int bdiv,
    long long sAh, long long sAl, long long sBh, long long sBl,
    long long sCh, long long sCl, int act)
{
    constexpr int WR = BM / 32;                       // warp rows
    constexpr int STAGE_B = (BM + 128) * ASTRIDE * 2; // bytes per stage
    extern __shared__ __half smh[];
    const int tid = threadIdx.x;
    const int wid = tid >> 5, lane = tid & 31;
    const int gid = lane >> 2, tig = lane & 3;
    const int wr = wid % WR, wc = wid / WR;

    int z = blockIdx.z;
    int zh = z / bdiv, zl = z % bdiv;
    A  += zh * sAh + zl * sAl;
    Bm += zh * sBh + zl * sBl;
    long long coff = zh * sCh + zl * sCl;

    int m0 = blockIdx.x * BM, n0 = blockIdx.y * 128;
    int mrem = M - m0, nrem = Nn - n0;
    const __half* Ag = A + (long long)m0 * lda;
    const __half* Bg = Bm + (long long)n0 * ldb;

    uint32_t smb = smem_u32(smh);

    // ldmatrix per-lane row offsets (halves)
    const int aRow = (wr * 32 + (lane & 15)) * ASTRIDE + (lane >> 4) * 8;
    const int mID = lane >> 3, rID = lane & 7;
    const int bRow = (((mID >> 1) << 3) + rID) * ASTRIDE + (mID & 1) * 8;  // within B tile (wc folded below)
    const int bColBase = wc * 64;

    float c[2][8][4];
    #pragma unroll
    for (int i = 0; i < 2; i++)
        #pragma unroll
        for (int j = 0; j < 8; j++)
            #pragma unroll
            for (int r = 0; r < 4; r++) c[i][j][r] = 0.f;

    const int NC = Kd >> 6;   // K chunks of 64

    #pragma unroll
    for (int s = 0; s < NSTAGE - 1; s++) {
        if (s < NC) {
            load_chunk<BM, NT>(Ag, mrem, lda, s << 6, smb + s * STAGE_B, tid);
            load_chunk<128, NT>(Bg, nrem, ldb, s << 6, smb + s * STAGE_B + BM * ASTRIDE * 2, tid);
        }
        cp_commit();
    }

    for (int ch = 0; ch < NC; ch++) {
        asm volatile("cp.async.wait_group %0;" :: "n"(NSTAGE - 2));
        __syncthreads();
        int pf = ch + NSTAGE - 1;
        if (pf < NC) {
            int s = pf % NSTAGE;
            load_chunk<BM, NT>(Ag, mrem, lda, pf << 6, smb + s * STAGE_B, tid);
            load_chunk<128, NT>(Bg, nrem, ldb, pf << 6, smb + s * STAGE_B + BM * ASTRIDE * 2, tid);
        }
        cp_commit();

        int cs = ch % NSTAGE;
        uint32_t aB = smb + cs * STAGE_B;
        uint32_t bB = aB + BM * ASTRIDE * 2 + (uint32_t)(bColBase * ASTRIDE) * 2u;

        #pragma unroll
        for (int ks = 0; ks < 4; ks++) {
            int kc = ks << 4;
            uint32_t a[2][4], b[8][2];
            #pragma unroll
            for (int i = 0; i < 2; i++) {
                uint32_t ad = aB + (uint32_t)(aRow + i * 16 * ASTRIDE + kc) * 2u;
                asm volatile("ldmatrix.sync.aligned.m8n8.x4.shared.b16 {%0,%1,%2,%3}, [%4];"
                    : "=r"(a[i][0]), "=r"(a[i][1]), "=r"(a[i][2]), "=r"(a[i][3]) : "r"(ad));
            }
            #pragma unroll
            for (int jp = 0; jp < 4; jp++) {
                uint32_t bd = bB + (uint32_t)(bRow + jp * 16 * ASTRIDE + kc) * 2u;
                asm volatile("ldmatrix.sync.aligned.m8n8.x4.shared.b16 {%0,%1,%2,%3}, [%4];"
                    : "=r"(b[2*jp][0]), "=r"(b[2*jp][1]),
                      "=r"(b[2*jp+1][0]), "=r"(b[2*jp+1][1]) : "r"(bd));
            }
            #pragma unroll
            for (int i = 0; i < 2; i++)
                #pragma unroll
                for (int j = 0; j < 8; j++) {
                    asm volatile(
                        "mma.sync.aligned.m16n8k16.row.col.f32.f16.f16.f32 "
                        "{%0,%1,%2,%3}, {%4,%5,%6,%7}, {%8,%9}, {%0,%1,%2,%3};"
                        : "+f"(c[i][j][0]), "+f"(c[i][j][1]),
                          "+f"(c[i][j][2]), "+f"(c[i][j][3])
                        : "r"(a[i][0]), "r"(a[i][1]), "r"(a[i][2]), "r"(a[i][3]),
                          "r"(b[j][0]), "r"(b[j][1]));
                }
        }
    }

    // epilogue
    const bool vec = (ldcc == 1);
    #pragma unroll
    for (int i = 0; i < 2; i++) {
        int rbase = wr * 32 + i * 16 + gid;
        #pragma unroll
        for (int half = 0; half < 2; half++) {
            int rloc = rbase + half * 8;
            if (rloc >= mrem) continue;
            long long row = m0 + rloc;
            #pragma unroll
            for (int j = 0; j < 8; j++) {
                int cloc = bColBase + j * 8 + tig * 2;
                bool ok0 = cloc < nrem, ok1 = cloc + 1 < nrem;
                if (!ok0) continue;
                int col = n0 + cloc;
                float v0 = c[i][j][half * 2], v1 = c[i][j][half * 2 + 1];
                if (bias) { v0 += bias[col]; if (ok1) v1 += bias[col + 1]; }
                if (act & 1) {
                    v0 = 0.5f * v0 * (1.f + erff(v0 * 0.70710678118654752f));
                    v1 = 0.5f * v1 * (1.f + erff(v1 * 0.70710678118654752f));
                }
                long long off = coff + row * ldcr + (long long)col * ldcc;
                if (act & 2) {
                    __half* Ch = (__half*)C;
                    if (vec && ok1) *(__half2*)(Ch + off) = __halves2half2(__float2half(v0), __float2half(v1));
                    else {
                        Ch[off] = __float2half(v0);
                        if (ok1) Ch[off + ldcc] = __float2half(v1);
                    }
                } else {
                    if (vec && ok1) *(float2*)(C + off) = make_float2(v0, v1);
                    else {
                        C[off] = v0;
                        if (ok1) C[off + ldcc] = v1;
                    }
                }
            }
        }
    }
}

// ---------------- all weights f32 -> f16 in one launch ----------------
#define SEG0 ((long long)CD*CS)
#define SEG1 (SEG0 + (long long)2*CD*CD)
#define SEG2 (SEG1 + (long long)2*CD*CD)
#define SEG3 (SEG2 + (long long)2*CD*CD)
#define SEG4 (SEG3 + (long long)2*CD*CD)
#define SEG5 (SEG4 + (long long)2*CDF*CD)
#define SEG6 (SEG5 + (long long)2*CDF*CD)
#define SEG7 (SEG6 + (long long)CP*CD)
__global__ void f2h_all(const float* __restrict__ s0, const float* __restrict__ s1,
                        const float* __restrict__ s2, const float* __restrict__ s3,
                        const float* __restrict__ s4, const float* __restrict__ s5,
                        const float* __restrict__ s6, const float* __restrict__ s7,
                        __half* __restrict__ out)
{
    long long i = (long long)blockIdx.x * blockDim.x + threadIdx.x;
    if (i >= SEG7) return;
    float v;
    if      (i < SEG0) v = s0[i];
    else if (i < SEG1) v = s1[i - SEG0];
    else if (i < SEG2) v = s2[i - SEG1];
    else if (i < SEG3) v = s3[i - SEG2];
    else if (i < SEG4) v = s4[i - SEG3];
    else if (i < SEG5) v = s5[i - SEG4];
    else if (i < SEG6) v = s6[i - SEG5];
    else               v = s7[i - SEG6];
    out[i] = __float2half(v);
}

// ---------------- per-(b,n) stats over S ----------------
__global__ void stats_kernel(const float* __restrict__ x, float* __restrict__ mean,
                             float* __restrict__ stdv)
{
    int bn = blockIdx.x;
    int b = bn / CN, n = bn % CN;
    const float* p = x + (long long)b * CS * CN + n;
    float s = 0.f, s2 = 0.f;
    for (int i = threadIdx.x; i < CS; i += blockDim.x) {
        float v = p[(long long)i * CN];
        s += v; s2 += v * v;
    }
    __shared__ float rs[128], rq[128];
    rs[threadIdx.x] = s; rq[threadIdx.x] = s2; __syncthreads();
    for (int o = 64; o > 0; o >>= 1) {
        if (threadIdx.x < o) { rs[threadIdx.x] += rs[threadIdx.x + o]; rq[threadIdx.x] += rq[threadIdx.x + o]; }
        __syncthreads();
    }
    if (threadIdx.x == 0) {
        float mu = rs[0] / CS;
        float var = rq[0] / CS - mu * mu;
        mean[bn] = mu;
        stdv[bn] = sqrtf(var + 1e-5f);
    }
}

__global__ void norm_t_kernel(const float* __restrict__ x, const float* __restrict__ mean,
                              const float* __restrict__ stdv, __half* __restrict__ xt)
{
    long long idx = (long long)blockIdx.x * blockDim.x + threadIdx.x;
    if (idx >= (long long)BND) return;
    int s = (int)(idx & (CS - 1));
    long long bn = idx >> 9;
    int b = (int)(bn / CN), n = (int)(bn % CN);
    xt[idx] = __float2half((x[((long long)b * CS + s) * CN + n] - mean[bn]) / stdv[bn]);
}

// ---------------- SWT decomposition (fp32 in, fp16 out) ----------------
__global__ void swt_dec_kernel(const float* __restrict__ h,
                               const float* __restrict__ f0g, const float* __restrict__ f1g,
                               __half* __restrict__ coef)
{
    int bn = blockIdx.x; int n = bn % CN;
    __shared__ float a[CD], b[CD];
    const float* hp = h + (long long)bn * CD;
    for (int d = threadIdx.x; d < CD; d += blockDim.x) a[d] = hp[d];
    float l0[3], l1[3];
    #pragma unroll
    for (int t = 0; t < 3; t++) { l0[t] = f0g[n * 3 + t]; l1[t] = f1g[n * 3 + t]; }
    __syncthreads();
    __half* cf = coef + (long long)bn * 4 * CD;
    for (int d = threadIdx.x; d < CD; d += blockDim.x) {
        int im = (d - 1) & 511, ip = (d + 1) & 511;
        cf[3 * CD + d] = __float2half(l1[0] * a[im] + l1[1] * a[d] + l1[2] * a[ip]);
        b[d]           = l0[0] * a[im] + l0[1] * a[d] + l0[2] * a[ip];
    }
    __syncthreads();
    for (int d = threadIdx.x; d < CD; d += blockDim.x) {
        int i0 = (d - 1) & 511, i1 = (d + 1) & 511, i2 = (d + 3) & 511;
        cf[2 * CD + d] = __float2half(l1[0] * b[i0] + l1[1] * b[i1] + l1[2] * b[i2]);
        a[d]           = l0[0] * b[i0] + l0[1] * b[i1] + l0[2] * b[i2];
    }
    __syncthreads();
    for (int d = threadIdx.x; d < CD; d += blockDim.x) {
        int i0 = (d - 2) & 511, i1 = (d + 2) & 511, i2 = (d + 6) & 511;
        cf[1 * CD + d] = __float2half(l1[0] * a[i0] + l1[1] * a[i1] + l1[2] * a[i2]);
        cf[0 * CD + d] = __float2half(l0[0] * a[i0] + l0[1] * a[i1] + l0[2] * a[i2]);
    }
}

// ---------------- SWT reconstruction (fp32 in, fp16 out) ----------------
__global__ void swt_rec_kernel(const float* __restrict__ c,
                               const float* __restrict__ g0g, const float* __restrict__ g1g,
                               __half* __restrict__ out)
{
    int bn = blockIdx.x; int n = bn % CN;
    const float* cp = c + (long long)bn * 4 * CD;
    __shared__ float a[CD], b[CD], det[CD];
    float f0[3], f1[3];
    #pragma unroll
    for (int t = 0; t < 3; t++) { f0[t] = g0g[n * 3 + t]; f1[t] = g1g[n * 3 + t]; }
    for (int d = threadIdx.x; d < CD; d += blockDim.x) { a[d] = cp[d]; det[d] = cp[CD + d]; }
    __syncthreads();
    for (int d = threadIdx.x; d < CD; d += blockDim.x) {
        int i0 = (d - 6) & 511, i1 = (d - 2) & 511, i2 = (d + 2) & 511;
        b[d] = 0.5f * (f0[0] * a[i0] + f0[1] * a[i1] + f0[2] * a[i2]
                     + f1[0] * det[i0] + f1[1] * det[i1] + f1[2] * det[i2]);
    }
    __syncthreads();
    for (int d = threadIdx.x; d < CD; d += blockDim.x) det[d] = cp[2 * CD + d];
    __syncthreads();
    for (int d = threadIdx.x; d < CD; d += blockDim.x) {
        int i0 = (d - 3) & 511, i1 = (d - 1) & 511, i2 = (d + 1) & 511;
        a[d] = 0.5f * (f0[0] * b[i0] + f0[1] * b[i1] + f0[2] * b[i2]
                     + f1[0] * det[i0] + f1[1] * det[i1] + f1[2] * det[i2]);
    }
    __syncthreads();
    for (int d = threadIdx.x; d < CD; d += blockDim.x) det[d] = cp[3 * CD + d];
    __syncthreads();
    __half* op = out + (long long)bn * CD;
    for (int d = threadIdx.x; d < CD; d += blockDim.x) {
        int i0 = (d - 1) & 511, i2 = (d + 1) & 511;
        op[d] = __float2half(0.5f * (f0[0] * a[i0] + f0[1] * a[d] + f0[2] * a[i2]
                                   + f1[0] * det[i0] + f1[1] * det[d] + f1[2] * det[i2]));
    }
}

// ---------------- transpose fp16 [b][n][m][e] -> [b][m][e][KPAD] ----------------
__global__ void trans_kernel(const __half* __restrict__ in, __half* __restrict__ out)
{
    int z = blockIdx.z; int b = z >> 2, m = z & 3;
    __shared__ __half t[32][34];
    int e0 = blockIdx.x * 32, n0 = blockIdx.y * 32;
    int tx = threadIdx.x, ty = threadIdx.y;
    #pragma unroll
    for (int j = 0; j < 4; j++) {
        int e = e0 + tx, n = n0 + ty + j * 8;
        t[ty + j * 8][tx] = (n < CN) ? in[(((long long)b * CN + n) * 4 + m) * CD + e]
                                     : __float2half(0.f);
    }
    __syncthreads();
    #pragma unroll
    for (int j = 0; j < 4; j++) {
        int n = n0 + tx, e = e0 + ty + j * 8;
        out[(((long long)b * 4 + m) * CD + e) * KPAD + n] = t[tx][ty + j * 8];
    }
}

// ---------------- row squared-norm (fp16 rows, stride KPAD) ----------------
__global__ void rowsq_kernel(const __half* __restrict__ in, float* __restrict__ out)
{
    int r = blockIdx.x;
    const __half* p = in + (long long)r * KPAD;
    float s = 0.f;
    for (int i = threadIdx.x; i < CN; i += blockDim.x) { float v = __half2float(p[i]); s += v * v; }
    __shared__ float rs[128];
    rs[threadIdx.x] = s; __syncthreads();
    for (int o = 64; o > 0; o >>= 1) {
        if (threadIdx.x < o) rs[threadIdx.x] += rs[threadIdx.x + o];
        __syncthreads();
    }
    if (threadIdx.x == 0) out[r] = rs[0];
}

// ---------------- wedge score + softmax (fp32 in, fp16 probs out) ----------------
__global__ void score_softmax_kernel(const float* __restrict__ dot,
                                     const float* __restrict__ qn2,
                                     const float* __restrict__ kn2,
                                     __half* __restrict__ prob)
{
    int row = blockIdx.x;
    int z = row >> 9;
    float q2 = qn2[row];
    const float* p = dot + (long long)row * CD;
    __half* pr = prob + (long long)row * CD;
    const float* k2 = kn2 + (long long)z * CD;
    const float scale = 1.f / sqrtf((float)CN);
    int t = threadIdx.x;
    float sc[2];
    float mx = -1e30f;
    #pragma unroll
    for (int j = 0; j < 2; j++) {
        int s = t + j * 256;
        float d = p[s];
        float w = sqrtf(fmaxf(q2 * k2[s] - d * d, 0.f) + 1e-8f);
        float v = ((1.f - ALPHA_) * d + ALPHA_ * w) * scale;
        sc[j] = v;
        mx = fmaxf(mx, v);
    }
    __shared__ float red[256];
    red[t] = mx; __syncthreads();
    for (int o = 128; o > 0; o >>= 1) {
        if (t < o) red[t] = fmaxf(red[t], red[t + o]);
        __syncthreads();
    }
    mx = red[0]; __syncthreads();
    float sum = 0.f;
    #pragma unroll
    for (int j = 0; j < 2; j++) { sc[j] = expf(sc[j] - mx); sum += sc[j]; }
    red[t] = sum; __syncthreads();
    for (int o = 128; o > 0; o >>= 1) {
        if (t < o) red[t] += red[t + o];
        __syncthreads();
    }
    float inv = 1.f / red[0];
    #pragma unroll
    for (int j = 0; j < 2; j++) pr[t + j * 256] = __float2half(sc[j] * inv);
}

// ---------------- add + layernorm ----------------
__global__ void add_ln_kernel(const float* __restrict__ x, const float* __restrict__ y,
                              const float* __restrict__ g, const float* __restrict__ bb,
                              float* __restrict__ out, __half* __restrict__ outh)
{
    int bn = blockIdx.x;
    const float* xp = x + (long long)bn * CD;
    const float* yp = y ? y + (long long)bn * CD : nullptr;
    int t = threadIdx.x;
    float v[2];
    float s = 0.f;
    #pragma unroll
    for (int j = 0; j < 2; j++) {
        int d = t + j * 256;
        v[j] = xp[d] + (yp ? yp[d] : 0.f);
        s += v[j];
    }
    __shared__ float red[256];
    red[t] = s; __syncthreads();
    for (int o = 128; o > 0; o >>= 1) { if (t < o) red[t] += red[t + o]; __syncthreads(); }
    float mu = red[0] / CD; __syncthreads();
    float s2 = 0.f;
    #pragma unroll
    for (int j = 0; j < 2; j++) { float dv = v[j] - mu; s2 += dv * dv; }
    red[t] = s2; __syncthreads();
    for (int o = 128; o > 0; o >>= 1) { if (t < o) red[t] += red[t + o]; __syncthreads(); }
    float inv = 1.f / sqrtf(red[0] / CD + 1e-5f);
    #pragma unroll
    for (int j = 0; j < 2; j++) {
        int d = t + j * 256;
        float r = (v[j] - mu) * inv * g[d] + bb[d];
        if (out)  out[(long long)bn * CD + d] = r;
        if (outh) outh[(long long)bn * CD + d] = __float2half(r);
    }
}

// ---------------- final output de-normalization ----------------
__global__ void out_kernel(const float* __restrict__ dec, const float* __restrict__ mean,
                           const float* __restrict__ stdv, float* __restrict__ out)
{
    int idx = blockIdx.x * blockDim.x + threadIdx.x;
    if (idx >= CB * CP * CN) return;
    int n = idx % CN;
    int p = (idx / CN) % CP;
    int b = idx / (CN * CP);
    int bn = b * CN + n;
    out[idx] = dec[(long long)bn * CP + p] * stdv[bn] + mean[bn];
}

__global__ void aux_out_kernel(const float* __restrict__ mean, const float* __restrict__ stdv,
                               float* __restrict__ out)
{
    int i = blockIdx.x * blockDim.x + threadIdx.x;
    if (i >= CBN) return;
    out[CB * CP * CN + i] = mean[i];
    out[CB * CP * CN + CBN + i] = stdv[i];
}

// ---------------- host orchestration ----------------
static void launch_tc(const __half* A, const __half* B, float* C, const float* bias,
                      int M, int Nn, int Kd, int lda, int ldb,
                      long long ldcr, long long ldcc,
                      int batches, int bdiv,
                      long long sAh, long long sAl,
                      long long sBh, long long sBl,
                      long long sCh, long long sCl, int act)
{
    long long b128 = (long long)((M + 127) / 128) * ((Nn + 127) / 128) * batches;
    if (b128 >= 296) {
        dim3 grid((M + 127) / 128, (Nn + 127) / 128, batches);
        gemm_tc<128, 256, 3><<<grid, 256, SMEM_128>>>(A, B, C, bias, M, Nn, Kd, lda, ldb,
            ldcr, ldcc, bdiv, sAh, sAl, sBh, sBl, sCh, sCl, act);
    } else {
        dim3 grid((M + 63) / 64, (Nn + 127) / 128, batches);
        gemm_tc<64, 128, 2><<<grid, 128, SMEM_64>>>(A, B, C, bias, M, Nn, Kd, lda, ldb,
            ldcr, ldcc, bdiv, sAh, sAl, sBh, sBl, sCh, sCl, act);
    }
}

extern "C" void kernel_launch(void* const* d_in, const int* in_sizes, int n_in,
                              void* d_out, int out_size)
{
    (void)in_sizes; (void)n_in;
    const float* x_enc  = (const float*)d_in[0];
    const float* emb_W  = (const float*)d_in[1];
    const float* emb_b  = (const float*)d_in[2];
    const float* h0     = (const float*)d_in[3];
    const float* h1     = (const float*)d_in[4];
    const float* g0     = (const float*)d_in[5];
    const float* g1     = (const float*)d_in[6];
    const float* Wq     = (const float*)d_in[7];
    const float* bq     = (const float*)d_in[8];
    const float* Wk     = (const float*)d_in[9];
    const float* bk     = (const float*)d_in[10];
    const float* Wv     = (const float*)d_in[11];
    const float* bv     = (const float*)d_in[12];
    const float* Wo     = (const float*)d_in[13];
    const float* bo     = (const float*)d_in[14];
    const float* W1     = (const float*)d_in[15];
    const float* b1     = (const float*)d_in[16];
    const float* W2     = (const float*)d_in[17];
    const float* b2     = (const float*)d_in[18];
    const float* ln1_g  = (const float*)d_in[19];
    const float* ln1_b  = (const float*)d_in[20];
    const float* ln2_g  = (const float*)d_in[21];
    const float* ln2_b  = (const float*)d_in[22];
    const float* lnf_g  = (const float*)d_in[23];
    const float* lnf_b  = (const float*)d_in[24];
    const float* proj_W = (const float*)d_in[25];
    const float* proj_b = (const float*)d_in[26];

    cudaFuncSetAttribute(gemm_tc<128, 256, 3>, cudaFuncAttributeMaxDynamicSharedMemorySize, SMEM_128);
    cudaFuncSetAttribute(gemm_tc<64, 128, 2>,  cudaFuncAttributeMaxDynamicSharedMemorySize, SMEM_64);

    float* ws = nullptr;
    cudaGetSymbolAddress((void**)&ws, g_ws);
    __half* hw = nullptr;
    cudaGetSymbolAddress((void**)&hw, g_hws);

    float* h    = ws + O_H;
    float* mean = ws + O_MEAN;
    float* stdv = ws + O_STD;
    float* dot  = ws + O_DOT;
    float* ao   = ws + O_AO;
    float* att  = ws + O_ATT;
    float* x1   = ws + O_X1;
    float* y2   = ws + O_Y2;
    float* dec  = ws + O_DEC;

    __half* xt_h  = hw + H_XT;
    __half* coefh = hw + H_COEF;
    __half* qh    = hw + H_Q;
    __half* kh    = hw + H_K;
    __half* vh    = hw + H_V;
    __half* qah   = hw + H_QA;
    __half* kah   = hw + H_KA;
    __half* prob  = hw + H_PROB;
    __half* rech  = hw + H_REC;
    __half* x1h   = hw + H_X1;
    __half* ffh   = hw + H_FF;
    __half* embWh = hw + H_EMBW;
    __half* Wqh   = hw + H_WQ;
    __half* Wkh   = hw + H_WK;
    __half* Wvh   = hw + H_WV;
    __half* Woh   = hw + H_WO;
    __half* W1h   = hw + H_W1;
    __half* W2h   = hw + H_W2;
    __half* pWh   = hw + H_PW;

    // qn2/kn2 borrow the front of ao: softmax consumes them before AV writes ao
    float* qn2b = ao;
    float* kn2b = ao + (size_t)CB * 4 * CD;

    f2h_all<<<(int)((SEG7 + 255) / 256), 256>>>(emb_W, Wq, Wk, Wv, Wo, W1, W2, proj_W, embWh);

    stats_kernel<<<CBN, 128>>>(x_enc, mean, stdv);
    norm_t_kernel<<<(int)((BND + 255) / 256), 256>>>(x_enc, mean, stdv, xt_h);

    launch_tc(xt_h, embWh, h, emb_b, CBN, CD, CS, CS, CS, CD, 1,
              1, 1, 0, 0, 0, 0, 0, 0, 0);

    const long long ZAP = (long long)CD * KPAD;
    const long long ZD  = (long long)CD * CD;
    const long long BSTR = (long long)CN * 4 * CD;

    for (int l = 0; l < 2; l++) {
        swt_dec_kernel<<<CBN, 256>>>(h, h0 + (long long)l * CN * 3, h1 + (long long)l * CN * 3, coefh);

        launch_tc(coefh, Wqh + (long long)l * CD * CD, (float*)qh, bq + (long long)l * CD,
                  CBN * 4, CD, CD, CD, CD, CD, 1, 1, 1, 0, 0, 0, 0, 0, 0, 2);
        launch_tc(coefh, Wkh + (long long)l * CD * CD, (float*)kh, bk + (long long)l * CD,
                  CBN * 4, CD, CD, CD, CD, CD, 1, 1, 1, 0, 0, 0, 0, 0, 0, 2);
        launch_tc(coefh, Wvh + (long long)l * CD * CD, (float*)vh, bv + (long long)l * CD,
                  CBN * 4, CD, CD, CD, CD, CD, 1, 1, 1, 0, 0, 0, 0, 0, 0, 2);

        {
            dim3 g2(16, KPAD / 32, CB * 4), b2d(32, 8);
            trans_kernel<<<g2, b2d>>>(qh, qah);
            trans_kernel<<<g2, b2d>>>(kh, kah);
        }
        rowsq_kernel<<<CB * 4 * CD, 128>>>(qah, qn2b);
        rowsq_kernel<<<CB * 4 * CD, 128>>>(kah, kn2b);

        launch_tc(qah, kah, dot, nullptr, CD, CD, KPAD, KPAD, KPAD, CD, 1,
                  CB * 4, 1, ZAP, 0, ZAP, 0, ZD, 0, 0);

        score_softmax_kernel<<<CB * 4 * CD, 256>>>(dot, qn2b, kn2b, prob);

        launch_tc(prob, vh, ao, nullptr, CD, CN, CD, CD, 4 * CD, 1, 4 * CD,
                  CB * 4, 4,
                  4 * ZD, ZD,
                  BSTR, CD,
                  BSTR, CD,
                  0);

        swt_rec_kernel<<<CBN, 256>>>(ao, g0 + (long long)l * CN * 3, g1 + (long long)l * CN * 3, rech);

        launch_tc(rech, Woh + (long long)l * CD * CD, att, bo + (long long)l * CD,
                  CBN, CD, CD, CD, CD, CD, 1, 1, 1, 0, 0, 0, 0, 0, 0, 0);

        add_ln_kernel<<<CBN, 256>>>(h, att, ln1_g + (long long)l * CD, ln1_b + (long long)l * CD, x1, x1h);

        launch_tc(x1h, W1h + (long long)l * CDF * CD, (float*)ffh, b1 + (long long)l * CDF,
                  CBN, CDF, CD, CD, CD, CDF, 1, 1, 1, 0, 0, 0, 0, 0, 0, 3);
        launch_tc(ffh, W2h + (long long)l * CD * CDF, y2, b2 + (long long)l * CD,
                  CBN, CD, CDF, CDF, CDF, CD, 1, 1, 1, 0, 0, 0, 0, 0, 0, 0);

        add_ln_kernel<<<CBN, 256>>>(x1, y2, ln2_g + (long long)l * CD, ln2_b + (long long)l * CD, h, nullptr);
    }

    add_ln_kernel<<<CBN, 256>>>(h, nullptr, lnf_g, lnf_b, nullptr, x1h);
    launch_tc(x1h, pWh, dec, proj_b, CBN, CP, CD, CD, CD, CP, 1,
              1, 1, 0, 0, 0, 0, 0, 0, 0);

    out_kernel<<<(CB * CP * CN + 255) / 256, 256>>>(dec, mean, stdv, (float*)d_out);
    if (out_size >= CB * CP * CN + 2 * CBN) {
        aux_out_kernel<<<(CBN + 255) / 256, 256>>>(mean, stdv, (float*)d_out);
    }
}